// round 1
// baseline (speedup 1.0000x reference)
#include <cuda_runtime.h>
#include <math.h>

// Problem constants
#define B_  64
#define N_  256
#define D_  512
#define E_  10
#define M_  (B_*N_)        // 16384 rows
#define KX_ (E_*D_)        // 5120  (edge part of K)
#define KT_ (KX_+D_)       // 5632  (edge + self)

// ---------------- scratch (device globals; no runtime allocation) ----------
__device__ unsigned g_bits[(size_t)E_*B_*N_*8];     // binary graphs, 256 bits/row
__device__ float    g_invneigh[M_];
__device__ float    g_w[M_];
__device__ float    g_X[(size_t)M_*KX_];            // gathered, /neigh-scaled
__device__ float    g_nodeA[(size_t)M_*D_];         // ping buffer for node
__device__ float    g_Wbig[(size_t)KT_*D_];         // [kk][d] transposed weights

// ---------------- K0a: build bitmask graphs -------------------------------
// one warp per (e,b,i) row; r = (e*B+b)*N + i
__global__ void k_bits(const int* __restrict__ adj, const int* __restrict__ mask) {
    int warp = threadIdx.x >> 5, lane = threadIdx.x & 31;
    int r = blockIdx.x * 8 + warp;
    int b = (r / N_) % B_;
    int i = r % N_;
    int mi = mask[b*N_ + i];
    const int* arow = adj + (size_t)r * N_;   // adj is laid out exactly as r*N
    unsigned keep = 0;
    #pragma unroll
    for (int c = 0; c < 8; c++) {
        int j = c*32 + lane;
        int bit = mi && mask[b*N_ + j] && arow[j] && (j != i);
        unsigned wrd = __ballot_sync(0xffffffffu, bit != 0);
        if (lane == c) keep = wrd;
    }
    if (lane < 8) g_bits[(size_t)r*8 + lane] = keep;
}

// ---------------- K0b: inv_neigh via popcount ------------------------------
__global__ void k_neigh() {
    int t = blockIdx.x*blockDim.x + threadIdx.x;   // t = b*N + i
    int b = t / N_, i = t % N_;
    int s = 0;
    for (int e = 0; e < E_; e++) {
        const unsigned* row = g_bits + (size_t)((e*B_+b)*N_+i)*8;
        #pragma unroll
        for (int c = 0; c < 8; c++) s += __popc(row[c]);
    }
    float n = (float)s; if (n < 1.f) n = 1.f;
    g_invneigh[t] = 1.f / n;
}

// ---------------- K0c: transpose weights into GEMM layout ------------------
// g_Wbig[kk*512 + d]: kk<5120 -> W_edge[e][d][k] (e=kk/512,k=kk%512); else W_self[d][kk-5120]
__global__ void k_transW(const float* __restrict__ Wedge, const float* __restrict__ Wself) {
    int idx = blockIdx.x*blockDim.x + threadIdx.x;
    if (idx >= KT_*D_) return;
    int kk = idx / D_, d = idx % D_;
    float v;
    if (kk < KX_) {
        int e = kk / D_, k = kk % D_;
        v = Wedge[((size_t)e*D_ + d)*D_ + k];
    } else {
        v = Wself[(size_t)d*D_ + (kk - KX_)];
    }
    g_Wbig[idx] = v;
}

// ---------------- K1: relatedness gate w ----------------------------------
// one warp per (b,n) row. useScratch: read node from g_nodeA instead of node0.
__global__ void k_w(const float* __restrict__ node0, int useScratch,
                    const float* __restrict__ Wnw, const float* __restrict__ bnw,
                    float* __restrict__ woutBase, int it) {
    int warp = threadIdx.x >> 5, lane = threadIdx.x & 31;
    int r = blockIdx.x*8 + warp;                 // b*N + n
    const float* node = useScratch ? g_nodeA : node0;
    const float4* nr = (const float4*)(node + (size_t)r*D_);
    const float4* wr = (const float4*)Wnw;
    float s = 0.f;
    #pragma unroll
    for (int c = 0; c < 4; c++) {
        float4 a = nr[c*32 + lane], w = wr[c*32 + lane];
        s += a.x*w.x + a.y*w.y + a.z*w.z + a.w*w.w;
    }
    #pragma unroll
    for (int o = 16; o; o >>= 1) s += __shfl_down_sync(0xffffffffu, s, o);
    if (lane == 0) {
        float z = s + bnw[0];
        float w = 1.f / (1.f + expf(-z));
        g_w[r] = w;
        int b = r / N_, n = r % N_;
        woutBase[(size_t)b*(2*N_) + it*N_ + n] = w;  // all_weight [B,2,N]
    }
}

// ---------------- K2: sparse gather X = (A_e @ (w .* node)) * inv_neigh ----
// one warp per (e,b,i); grid order r=(b*E+e)*N+i keeps node[b] (512KB) L2-hot
__global__ void k_gather(const float* __restrict__ node0, int useScratch) {
    int warp = threadIdx.x >> 5, lane = threadIdx.x & 31;
    int r = blockIdx.x*8 + warp;
    int b = r / (E_*N_);
    int e = (r / N_) % E_;
    int i = r % N_;
    const float* node = useScratch ? g_nodeA : node0;
    const unsigned* brow = g_bits + (size_t)((e*B_+b)*N_+i)*8;
    float4 acc[4];
    #pragma unroll
    for (int q = 0; q < 4; q++) acc[q] = make_float4(0.f,0.f,0.f,0.f);
    const float* nb = node + (size_t)b*N_*D_;
    #pragma unroll
    for (int c = 0; c < 8; c++) {
        unsigned w32 = brow[c];
        while (w32) {
            int jj = __ffs(w32) - 1;
            w32 &= (w32 - 1);
            int j = c*32 + jj;
            float wj = g_w[b*N_ + j];
            const float4* np = (const float4*)(nb + (size_t)j*D_);
            #pragma unroll
            for (int q = 0; q < 4; q++) {
                float4 v = np[q*32 + lane];
                acc[q].x += wj*v.x; acc[q].y += wj*v.y;
                acc[q].z += wj*v.z; acc[q].w += wj*v.w;
            }
        }
    }
    float inv = g_invneigh[b*N_ + i];
    float4* xp = (float4*)(g_X + (size_t)(b*N_+i)*KX_ + (size_t)e*D_);
    #pragma unroll
    for (int q = 0; q < 4; q++) {
        acc[q].x *= inv; acc[q].y *= inv; acc[q].z *= inv; acc[q].w *= inv;
        xp[q*32 + lane] = acc[q];
    }
}

// ---------------- K3: fused GEMM + bias + relu -----------------------------
// C[16384,512] = [X | node] @ g_Wbig + b_self, relu
// 128x128 tile, BK=8, 8x8 microtile, 256 threads
__global__ void __launch_bounds__(256, 2)
k_gemm(const float* __restrict__ node0, int inScratch,
       const float* __restrict__ bself, float* __restrict__ out0, int outScratch) {
    __shared__ float As[8][128];
    __shared__ float Bs[8][128];
    const float* nodeIn = inScratch ? g_nodeA : node0;
    float* out = outScratch ? g_nodeA : out0;

    int t = threadIdx.x;
    int mBase = blockIdx.y * 128;
    int dBase = blockIdx.x * 128;

    int aRow = t >> 1;             // 0..127
    int aCol = (t & 1) * 4;        // 0 or 4
    int bRow = t >> 5;             // 0..7
    int bCol = (t & 31) * 4;       // 0..124
    int tr = (t >> 4) * 8;         // microtile row offset
    int tc = (t & 15) * 8;         // microtile col offset

    float acc[8][8];
    #pragma unroll
    for (int ii = 0; ii < 8; ii++)
        #pragma unroll
        for (int jj = 0; jj < 8; jj++) acc[ii][jj] = 0.f;

    const float* xrow = g_X    + (size_t)(mBase + aRow)*KX_;
    const float* nrow = nodeIn + (size_t)(mBase + aRow)*D_;

    for (int kk0 = 0; kk0 < KT_; kk0 += 8) {
        int kk = kk0 + aCol;
        float4 av;
        if (kk < KX_) av = *(const float4*)(xrow + kk);
        else          av = *(const float4*)(nrow + (kk - KX_));
        As[aCol+0][aRow] = av.x;
        As[aCol+1][aRow] = av.y;
        As[aCol+2][aRow] = av.z;
        As[aCol+3][aRow] = av.w;

        float4 bv = *(const float4*)(g_Wbig + (size_t)(kk0 + bRow)*D_ + dBase + bCol);
        *(float4*)(&Bs[bRow][bCol]) = bv;
        __syncthreads();

        #pragma unroll
        for (int k = 0; k < 8; k++) {
            float ra[8], rb[8];
            *(float4*)(ra)   = *(const float4*)(&As[k][tr]);
            *(float4*)(ra+4) = *(const float4*)(&As[k][tr+4]);
            *(float4*)(rb)   = *(const float4*)(&Bs[k][tc]);
            *(float4*)(rb+4) = *(const float4*)(&Bs[k][tc+4]);
            #pragma unroll
            for (int ii = 0; ii < 8; ii++)
                #pragma unroll
                for (int jj = 0; jj < 8; jj++)
                    acc[ii][jj] += ra[ii]*rb[jj];
        }
        __syncthreads();
    }

    #pragma unroll
    for (int ii = 0; ii < 8; ii++) {
        int m = mBase + tr + ii;
        float* orow = out + (size_t)m*D_ + dBase + tc;
        float4 v0, v1;
        float tmp[8];
        #pragma unroll
        for (int jj = 0; jj < 8; jj++) {
            float v = acc[ii][jj] + bself[dBase + tc + jj];
            tmp[jj] = v > 0.f ? v : 0.f;
        }
        v0 = make_float4(tmp[0], tmp[1], tmp[2], tmp[3]);
        v1 = make_float4(tmp[4], tmp[5], tmp[6], tmp[7]);
        *(float4*)(orow)     = v0;
        *(float4*)(orow + 4) = v1;
    }
}

// ---------------- launch ---------------------------------------------------
extern "C" void kernel_launch(void* const* d_in, const int* in_sizes, int n_in,
                              void* d_out, int out_size) {
    const float* node  = (const float*)d_in[0];
    const float* Wnw   = (const float*)d_in[1];
    const float* bnw   = (const float*)d_in[2];
    const float* Wself = (const float*)d_in[3];
    const float* bself = (const float*)d_in[4];
    const float* Wedge = (const float*)d_in[5];
    const int*   mask  = (const int*)d_in[6];
    const int*   adj   = (const int*)d_in[7];

    float* out  = (float*)d_out;
    float* outW = out + (size_t)M_*D_;   // all_weight region [B,2,N]

    // iteration-invariant preprocessing
    k_transW<<<(KT_*D_ + 255)/256, 256>>>(Wedge, Wself);
    k_bits  <<<(E_*B_*N_)/8, 256>>>(adj, mask);
    k_neigh <<<M_/256, 256>>>();

    // ---- iteration 0: node(in) -> g_nodeA ----
    k_w     <<<M_/8, 256>>>(node, 0, Wnw, bnw, outW, 0);
    k_gather<<<(E_*B_*N_)/8, 256>>>(node, 0);
    k_gemm  <<<dim3(4, 128), 256>>>(node, 0, bself, out, 1 /*-> g_nodeA*/);

    // ---- iteration 1: g_nodeA -> d_out ----
    k_w     <<<M_/8, 256>>>(node, 1, Wnw, bnw, outW, 1);
    k_gather<<<(E_*B_*N_)/8, 256>>>(node, 1);
    k_gemm  <<<dim3(4, 128), 256>>>(node, 1, bself, out, 0 /*-> d_out*/);
}

// round 3
// speedup vs baseline: 1.4065x; 1.4065x over previous
#include <cuda_runtime.h>
#include <cuda_bf16.h>
#include <math.h>
#include <stdint.h>

// ---------------- problem constants ----------------
#define B_  64
#define N_  256
#define D_  512
#define E_  10
#define M_  (B_*N_)        // 16384
#define KX_ (E_*D_)        // 5120
#define KT_ (KX_+D_)       // 5632
#define KS_ (3*KT_)        // 16896 (bf16x3-stacked K for stage B)
#define KI_B (KS_/32)      // 528 k-iters (stage B)
#define KI_A 16            // k-iters (stage A, K=512)

typedef __nv_bfloat16 bf16;

// ---------------- device scratch (static; no runtime allocation) ----------
__device__ unsigned g_bits[(size_t)E_*B_*N_*8];
__device__ float    g_invneigh[M_];
__device__ float    g_w[M_];
__device__ float    g_nodeA[(size_t)M_*D_];          // fp32 node ping buffer
__device__ bf16     g_G[(size_t)E_*B_*N_*N_];        // dense 0/1 graphs (exact bf16)
__device__ bf16     g_Bstack[(size_t)D_*KS_];        // [d][part*5632+kk] = Whi|Wlo|Whi
__device__ bf16     g_Zt[(size_t)B_*D_*2*N_];        // [b][d][k] k<256:hi(j=k) else lo
__device__ bf16     g_Xhi[(size_t)M_*KX_];
__device__ bf16     g_Xlo[(size_t)M_*KX_];
__device__ bf16     g_nhi[(size_t)M_*D_];
__device__ bf16     g_nlo[(size_t)M_*D_];

// ---------------- mma.sync helpers (portable compute_103) -------------------
__device__ __forceinline__ uint32_t smem_u32(const void* p){
    uint32_t a; asm("{ .reg .u64 t; cvta.to.shared.u64 t, %1; cvt.u32.u64 %0, t; }"
                    : "=r"(a) : "l"(p)); return a;
}
__device__ __forceinline__ void cpa16(uint32_t dst, const void* src){
    asm volatile("cp.async.cg.shared.global [%0], [%1], 16;" :: "r"(dst), "l"(src));
}
#define CP_COMMIT() asm volatile("cp.async.commit_group;" ::: "memory")
#define CP_WAIT1()  asm volatile("cp.async.wait_group 1;" ::: "memory")

__device__ __forceinline__ void ldsm_x4(uint32_t* r, uint32_t addr){
    asm volatile("ldmatrix.sync.aligned.m8n8.x4.shared.b16 {%0,%1,%2,%3}, [%4];"
        : "=r"(r[0]),"=r"(r[1]),"=r"(r[2]),"=r"(r[3]) : "r"(addr));
}
__device__ __forceinline__ void mma16816(float* c, const uint32_t* a, const uint32_t* b){
    asm volatile("mma.sync.aligned.m16n8k16.row.col.f32.bf16.bf16.f32 "
        "{%0,%1,%2,%3},{%4,%5,%6,%7},{%8,%9},{%0,%1,%2,%3};"
        : "+f"(c[0]),"+f"(c[1]),"+f"(c[2]),"+f"(c[3])
        : "r"(a[0]),"r"(a[1]),"r"(a[2]),"r"(a[3]), "r"(b[0]),"r"(b[1]));
}

// smem: 3 stages; per stage As[128][40] + Bs[128][40] bf16 (80B pitch:
// 8 consecutive rows hit disjoint 4-bank groups -> conflict-free ldmatrix)
#define STAGE_BYTES 20480
#define SMEM_DYN    (3*STAGE_BYTES)

// warp-level inner product on one (As,Bs) stage: 64x32 warp tile, k=32
__device__ __forceinline__ void warp_compute(uint32_t sA, uint32_t sB,
                                             int m_off, int n_off,
                                             float c[4][4][4], int lane){
    #pragma unroll
    for (int kh = 0; kh < 2; ++kh){
        int k16 = kh*16;
        uint32_t a[4][4];
        #pragma unroll
        for (int mt = 0; mt < 4; ++mt){
            int row = m_off + mt*16 + (lane & 15);
            ldsm_x4(a[mt], sA + (uint32_t)(row*40 + k16 + ((lane>>4)<<3))*2);
        }
        uint32_t bfr[2][4];
        #pragma unroll
        for (int np = 0; np < 2; ++np){
            int row = n_off + np*16 + (lane & 7) + ((lane>>4)&1)*8;
            ldsm_x4(bfr[np], sB + (uint32_t)(row*40 + k16 + (((lane>>3)&1)<<3))*2);
        }
        #pragma unroll
        for (int mt = 0; mt < 4; ++mt)
            #pragma unroll
            for (int nt = 0; nt < 4; ++nt)
                mma16816(c[mt][nt], a[mt], &bfr[nt>>1][(nt&1)*2]);
    }
}

// ---------------- preprocessing kernels ------------------------------------
__global__ void k_bits(const int* __restrict__ adj, const int* __restrict__ mask){
    int warp = threadIdx.x >> 5, lane = threadIdx.x & 31;
    int r = blockIdx.x * 8 + warp;
    int b = (r / N_) % B_;
    int i = r % N_;
    int mi = mask[b*N_ + i];
    const int* arow = adj + (size_t)r * N_;
    unsigned keep = 0;
    #pragma unroll
    for (int c = 0; c < 8; c++){
        int j = c*32 + lane;
        int bit = mi && mask[b*N_ + j] && arow[j] && (j != i);
        unsigned wrd = __ballot_sync(0xffffffffu, bit != 0);
        if (lane == c) keep = wrd;
    }
    if (lane < 8) g_bits[(size_t)r*8 + lane] = keep;
}
__global__ void k_neigh(){
    int t = blockIdx.x*blockDim.x + threadIdx.x;
    int b = t / N_;
    int s = 0;
    for (int e = 0; e < E_; e++){
        const unsigned* row = g_bits + (size_t)((e*B_+b)*N_ + (t % N_))*8;
        #pragma unroll
        for (int c = 0; c < 8; c++) s += __popc(row[c]);
    }
    float n = (float)s; if (n < 1.f) n = 1.f;
    g_invneigh[t] = 1.f / n;
}
__global__ void k_gdense(const int* __restrict__ adj, const int* __restrict__ mask){
    size_t idx = (size_t)blockIdx.x*256 + threadIdx.x;
    int j = (int)(idx & 255);
    size_t t = idx >> 8;
    int i = (int)(t & 255); t >>= 8;
    int b = (int)(t & 63);
    int v = adj[idx] && mask[b*N_+i] && mask[b*N_+j] && (i != j);
    g_G[idx] = __float2bfloat16(v ? 1.f : 0.f);
}
__global__ void k_bstack(const float* __restrict__ We, const float* __restrict__ Ws){
    int idx = blockIdx.x*256 + threadIdx.x;
    if (idx >= D_*KT_) return;
    int d = idx / KT_, kk = idx % KT_;
    float w;
    if (kk < KX_){ int e = kk / D_, k2 = kk % D_; w = We[((size_t)e*D_ + d)*D_ + k2]; }
    else w = Ws[(size_t)d*D_ + (kk - KX_)];
    bf16 h = __float2bfloat16(w);
    bf16 l = __float2bfloat16(w - __bfloat162float(h));
    size_t base = (size_t)d*KS_;
    g_Bstack[base + kk] = h;
    g_Bstack[base + KT_ + kk] = l;
    g_Bstack[base + 2*KT_ + kk] = h;
}

// ---------------- per-iteration elementwise kernels -------------------------
__global__ void k_w(const float* __restrict__ node0, int useScratch,
                    const float* __restrict__ Wnw, const float* __restrict__ bnw,
                    float* __restrict__ woutBase, int it){
    int warp = threadIdx.x >> 5, lane = threadIdx.x & 31;
    int r = blockIdx.x*8 + warp;
    const float* node = useScratch ? g_nodeA : node0;
    const float4* nr = (const float4*)(node + (size_t)r*D_);
    const float4* wr = (const float4*)Wnw;
    float s = 0.f;
    #pragma unroll
    for (int c = 0; c < 4; c++){
        float4 a = nr[c*32 + lane], w = wr[c*32 + lane];
        s += a.x*w.x + a.y*w.y + a.z*w.z + a.w*w.w;
    }
    #pragma unroll
    for (int o = 16; o; o >>= 1) s += __shfl_down_sync(0xffffffffu, s, o);
    if (lane == 0){
        float z = s + bnw[0];
        float w = 1.f / (1.f + expf(-z));
        g_w[r] = w;
        int b = r / N_, n = r % N_;
        woutBase[(size_t)b*(2*N_) + it*N_ + n] = w;
    }
}
__global__ void k_split(const float* __restrict__ node0, int useScratch){
    int idx = blockIdx.x*256 + threadIdx.x;
    const float* src = useScratch ? g_nodeA : node0;
    float v = src[idx];
    bf16 h = __float2bfloat16(v);
    g_nhi[idx] = h;
    g_nlo[idx] = __float2bfloat16(v - __bfloat162float(h));
}
__global__ void k_zt(const float* __restrict__ node0, int useScratch){
    __shared__ float s[32][33];
    const float* node = useScratch ? g_nodeA : node0;
    int b = blockIdx.z, d0 = blockIdx.x*32, j0 = blockIdx.y*32;
    int tx = threadIdx.x, ty = threadIdx.y;
    int j = j0 + ty;
    s[ty][tx] = node[((size_t)b*N_ + j)*D_ + d0 + tx] * g_w[b*N_ + j];
    __syncthreads();
    float v = s[tx][ty];
    bf16 h = __float2bfloat16(v);
    bf16 l = __float2bfloat16(v - __bfloat162float(h));
    size_t base = ((size_t)b*D_ + d0 + ty) * (size_t)(2*N_);
    g_Zt[base + j0 + tx] = h;
    g_Zt[base + N_ + j0 + tx] = l;
}

// ---------------- stage A GEMM: X = (G @ Zt) * inv_neigh -> Xhi/Xlo ---------
__global__ void __launch_bounds__(256, 1) k_gemmA(){
    extern __shared__ char dsm[];
    uint32_t sbase = smem_u32(dsm);
    int tid = threadIdx.x, wid = tid >> 5, lane = tid & 31;
    int dBase = blockIdx.x * 128;          // 0..383 step 128 over D=512 (x=4)
    int y = blockIdx.y;                     // be*2 + mt128
    int mt128 = y & 1; int be = y >> 1;
    int e = be % E_, b = be / E_;
    int m_off = (wid >> 2) * 64;
    int n_off = (wid & 3) * 32;

    const bf16* Gbase = g_G + (((size_t)e*B_ + b)*N_ + (size_t)mt128*128) * N_;
    const bf16* Zbase = g_Zt + ((size_t)b*D_ + dBase) * (size_t)(2*N_);

    int r0 = tid >> 1;                      // row handled by this thread
    int c0 = (tid & 1) * 2;                 // first 16B chunk (of 4)

    // load stage s for k-iter itk
    auto load = [&](int itk, int s){
        uint32_t sA = sbase + s*STAGE_BYTES;
        uint32_t sB = sA + 10240;
        int k0 = itk * 32;
        int gcol = k0 & 255;                // G col (j) wraps hi/lo halves
        #pragma unroll
        for (int j = 0; j < 2; ++j){
            int c = c0 + j;
            cpa16(sA + (uint32_t)(r0*40 + c*8)*2, Gbase + (size_t)r0*N_ + gcol + c*8);
            cpa16(sB + (uint32_t)(r0*40 + c*8)*2, Zbase + (size_t)r0*(2*N_) + k0 + c*8);
        }
        CP_COMMIT();
    };

    float c[4][4][4];
    #pragma unroll
    for (int i = 0; i < 4; ++i)
        #pragma unroll
        for (int j2 = 0; j2 < 4; ++j2)
            #pragma unroll
            for (int q = 0; q < 4; ++q) c[i][j2][q] = 0.f;

    load(0, 0); load(1, 1);
    for (int it = 0; it < KI_A; ++it){
        CP_WAIT1();
        __syncthreads();
        if (it + 2 < KI_A) load(it + 2, (it + 2) % 3); else CP_COMMIT();
        int s = it % 3;
        warp_compute(sbase + s*STAGE_BYTES, sbase + s*STAGE_BYTES + 10240,
                     m_off, n_off, c, lane);
        __syncthreads();
    }

    // epilogue: scale by inv_neigh, split hi/lo bf16, store packed u32
    #pragma unroll
    for (int mt = 0; mt < 4; ++mt){
        int i1 = mt128*128 + m_off + mt*16 + (lane >> 2);
        int r1 = b*N_ + i1;
        float inv1 = g_invneigh[r1];
        float inv2 = g_invneigh[r1 + 8];
        #pragma unroll
        for (int nt = 0; nt < 4; ++nt){
            int col = e*D_ + dBase + n_off + nt*8 + (lane & 3)*2;
            float x0 = c[mt][nt][0]*inv1, x1 = c[mt][nt][1]*inv1;
            float x2 = c[mt][nt][2]*inv2, x3 = c[mt][nt][3]*inv2;
            bf16 h0=__float2bfloat16(x0), h1=__float2bfloat16(x1);
            bf16 h2=__float2bfloat16(x2), h3=__float2bfloat16(x3);
            bf16 l0=__float2bfloat16(x0-__bfloat162float(h0));
            bf16 l1=__float2bfloat16(x1-__bfloat162float(h1));
            bf16 l2=__float2bfloat16(x2-__bfloat162float(h2));
            bf16 l3=__float2bfloat16(x3-__bfloat162float(h3));
            uint32_t hw0=(uint32_t)__bfloat16_as_ushort(h0)|((uint32_t)__bfloat16_as_ushort(h1)<<16);
            uint32_t hw1=(uint32_t)__bfloat16_as_ushort(h2)|((uint32_t)__bfloat16_as_ushort(h3)<<16);
            uint32_t lw0=(uint32_t)__bfloat16_as_ushort(l0)|((uint32_t)__bfloat16_as_ushort(l1)<<16);
            uint32_t lw1=(uint32_t)__bfloat16_as_ushort(l2)|((uint32_t)__bfloat16_as_ushort(l3)<<16);
            *(uint32_t*)(g_Xhi + (size_t)r1*KX_ + col)       = hw0;
            *(uint32_t*)(g_Xhi + (size_t)(r1+8)*KX_ + col)   = hw1;
            *(uint32_t*)(g_Xlo + (size_t)r1*KX_ + col)       = lw0;
            *(uint32_t*)(g_Xlo + (size_t)(r1+8)*KX_ + col)   = lw1;
        }
    }
}

// ---------------- stage B GEMM: out = relu([X|n]x3 @ Bstack + bias) ---------
__global__ void __launch_bounds__(256, 1) k_gemmB(const float* __restrict__ bself,
                                                  float* __restrict__ out0, int outScratch){
    extern __shared__ char dsm[];
    uint32_t sbase = smem_u32(dsm);
    int tid = threadIdx.x, wid = tid >> 5, lane = tid & 31;
    int dBase = blockIdx.x * 128;
    int mBase = blockIdx.y * 128;
    int m_off = (wid >> 2) * 64;
    int n_off = (wid & 3) * 32;

    int r0 = tid >> 1;
    int c0 = (tid & 1) * 2;

    auto load = [&](int itk, int s){
        uint32_t sA = sbase + s*STAGE_BYTES;
        uint32_t sB = sA + 10240;
        int part = itk / 176;
        int rr = (itk - part*176) * 32;
        const bf16* Ab; size_t ap;
        if (rr < KX_){ Ab = (part < 2 ? g_Xhi : g_Xlo) + (size_t)mBase*KX_ + rr; ap = KX_; }
        else         { Ab = (part < 2 ? g_nhi : g_nlo) + (size_t)mBase*D_ + (rr - KX_); ap = D_; }
        const bf16* Bb = g_Bstack + (size_t)(dBase)*KS_ + (size_t)itk*32;
        #pragma unroll
        for (int j = 0; j < 2; ++j){
            int c = c0 + j;
            cpa16(sA + (uint32_t)(r0*40 + c*8)*2, Ab + (size_t)r0*ap + c*8);
            cpa16(sB + (uint32_t)(r0*40 + c*8)*2, Bb + (size_t)r0*KS_ + c*8);
        }
        CP_COMMIT();
    };

    float c[4][4][4];
    #pragma unroll
    for (int i = 0; i < 4; ++i)
        #pragma unroll
        for (int j2 = 0; j2 < 4; ++j2)
            #pragma unroll
            for (int q = 0; q < 4; ++q) c[i][j2][q] = 0.f;

    load(0, 0); load(1, 1);
    for (int it = 0; it < KI_B; ++it){
        CP_WAIT1();
        __syncthreads();
        if (it + 2 < KI_B) load(it + 2, (it + 2) % 3); else CP_COMMIT();
        int s = it % 3;
        warp_compute(sbase + s*STAGE_BYTES, sbase + s*STAGE_BYTES + 10240,
                     m_off, n_off, c, lane);
        __syncthreads();
    }

    float* out = outScratch ? g_nodeA : out0;
    #pragma unroll
    for (int mt = 0; mt < 4; ++mt){
        int m1 = mBase + m_off + mt*16 + (lane >> 2);
        #pragma unroll
        for (int nt = 0; nt < 4; ++nt){
            int n = dBase + n_off + nt*8 + (lane & 3)*2;
            float bi0 = __ldg(bself + n), bi1 = __ldg(bself + n + 1);
            float v0 = c[mt][nt][0] + bi0, v1 = c[mt][nt][1] + bi1;
            float v2 = c[mt][nt][2] + bi0, v3 = c[mt][nt][3] + bi1;
            v0 = v0 > 0.f ? v0 : 0.f; v1 = v1 > 0.f ? v1 : 0.f;
            v2 = v2 > 0.f ? v2 : 0.f; v3 = v3 > 0.f ? v3 : 0.f;
            *(float2*)(out + (size_t)m1*D_ + n)     = make_float2(v0, v1);
            *(float2*)(out + (size_t)(m1+8)*D_ + n) = make_float2(v2, v3);
        }
    }
}

// ---------------- launch ----------------------------------------------------
extern "C" void kernel_launch(void* const* d_in, const int* in_sizes, int n_in,
                              void* d_out, int out_size){
    const float* node  = (const float*)d_in[0];
    const float* Wnw   = (const float*)d_in[1];
    const float* bnw   = (const float*)d_in[2];
    const float* Wself = (const float*)d_in[3];
    const float* bself = (const float*)d_in[4];
    const float* Wedge = (const float*)d_in[5];
    const int*   mask  = (const int*)d_in[6];
    const int*   adj   = (const int*)d_in[7];

    float* out  = (float*)d_out;
    float* outW = out + (size_t)M_*D_;

    cudaFuncSetAttribute(k_gemmA, cudaFuncAttributeMaxDynamicSharedMemorySize, SMEM_DYN);
    cudaFuncSetAttribute(k_gemmB, cudaFuncAttributeMaxDynamicSharedMemorySize, SMEM_DYN);

    // iteration-invariant preprocessing
    k_bstack<<<(D_*KT_ + 255)/256, 256>>>(Wedge, Wself);
    k_bits  <<<(E_*B_*N_)/8, 256>>>(adj, mask);
    k_neigh <<<M_/256, 256>>>();
    k_gdense<<<(int)(((size_t)E_*B_*N_*N_)/256), 256>>>(adj, mask);

    // ---- iteration 0: node -> g_nodeA ----
    k_w    <<<M_/8, 256>>>(node, 0, Wnw, bnw, outW, 0);
    k_split<<<(M_*D_)/256, 256>>>(node, 0);
    k_zt   <<<dim3(16, 8, B_), dim3(32, 32)>>>(node, 0);
    k_gemmA<<<dim3(4, B_*E_*2), 256, SMEM_DYN>>>();
    k_gemmB<<<dim3(4, M_/128), 256, SMEM_DYN>>>(bself, out, 1);

    // ---- iteration 1: g_nodeA -> d_out ----
    k_w    <<<M_/8, 256>>>(node, 1, Wnw, bnw, outW, 1);
    k_split<<<(M_*D_)/256, 256>>>(node, 1);
    k_zt   <<<dim3(16, 8, B_), dim3(32, 32)>>>(node, 1);
    k_gemmA<<<dim3(4, B_*E_*2), 256, SMEM_DYN>>>();
    k_gemmB<<<dim3(4, M_/128), 256, SMEM_DYN>>>(bself, out, 0);
}

// round 4
// speedup vs baseline: 1.5407x; 1.0954x over previous
#include <cuda_runtime.h>
#include <cuda_fp16.h>
#include <math.h>
#include <stdint.h>

// ---------------- problem constants ----------------
#define B_  64
#define N_  256
#define D_  512
#define E_  10
#define M_  (B_*N_)        // 16384
#define KX_ (E_*D_)        // 5120
#define KT_ (KX_+D_)       // 5632
#define KS_ (3*KT_)        // 16896 (fp16x3-stacked K for stage B)
#define KI_B (KS_/32)      // 528 k-iters (stage B)
#define KI_A 16            // k-iters (stage A, K=512)

typedef __half fp16;

// ---------------- device scratch (static; no runtime allocation) ----------
__device__ unsigned g_bits[(size_t)E_*B_*N_*8];      // binary graphs bitmask
__device__ float    g_invneigh[M_];
__device__ float    g_w[M_];
__device__ float    g_nodeA[(size_t)M_*D_];          // fp32 node ping buffer
__device__ fp16     g_Bstack[(size_t)D_*KS_];        // [d][part*5632+kk]: Whi|Whi|Wlo
__device__ fp16     g_Zt[(size_t)B_*D_*2*N_];        // [b][d][k] k<256:hi(j) else lo
__device__ fp16     g_Xhi[(size_t)M_*KX_];
__device__ fp16     g_Xlo[(size_t)M_*KX_];
__device__ fp16     g_nhi[(size_t)M_*D_],  g_nlo[(size_t)M_*D_];
__device__ fp16     g_nhi2[(size_t)M_*D_], g_nlo2[(size_t)M_*D_];

// ---------------- PTX helpers ----------------------------------------------
__device__ __forceinline__ uint32_t smem_u32(const void* p){
    uint32_t a; asm("{ .reg .u64 t; cvta.to.shared.u64 t, %1; cvt.u32.u64 %0, t; }"
                    : "=r"(a) : "l"(p)); return a;
}
__device__ __forceinline__ void cpa16(uint32_t dst, const void* src){
    asm volatile("cp.async.cg.shared.global [%0], [%1], 16;" :: "r"(dst), "l"(src));
}
#define CP_COMMIT() asm volatile("cp.async.commit_group;" ::: "memory")
#define CP_WAIT2()  asm volatile("cp.async.wait_group 2;" ::: "memory")

__device__ __forceinline__ void ldsm_x4(uint32_t* r, uint32_t addr){
    asm volatile("ldmatrix.sync.aligned.m8n8.x4.shared.b16 {%0,%1,%2,%3}, [%4];"
        : "=r"(r[0]),"=r"(r[1]),"=r"(r[2]),"=r"(r[3]) : "r"(addr));
}
__device__ __forceinline__ void mma16816(float* c, const uint32_t* a, const uint32_t* b){
    asm volatile("mma.sync.aligned.m16n8k16.row.col.f32.f16.f16.f32 "
        "{%0,%1,%2,%3},{%4,%5,%6,%7},{%8,%9},{%0,%1,%2,%3};"
        : "+f"(c[0]),"+f"(c[1]),"+f"(c[2]),"+f"(c[3])
        : "r"(a[0]),"r"(a[1]),"r"(a[2]),"r"(a[3]), "r"(b[0]),"r"(b[1]));
}

// smem: 4 stages; per stage As[128][40] + Bs[256][40] fp16 (80B pitch ->
// 8 consecutive rows hit distinct bank groups, conflict-free ldmatrix)
#define STG_BYTES 30720
#define OFF_B     10240
#define SMEM_DYN  (4*STG_BYTES)

// warp tile 64x64 (8 warps: 2 m x 4 n over 128x256 CTA tile)
__device__ __forceinline__ void warp_compute(uint32_t sA, uint32_t sB,
                                             int m_off, int n_off,
                                             float c[4][8][4], int lane){
    #pragma unroll
    for (int kh = 0; kh < 2; ++kh){
        int k16 = kh*16;
        uint32_t a[4][4];
        #pragma unroll
        for (int mt = 0; mt < 4; ++mt){
            int row = m_off + mt*16 + (lane & 15);
            ldsm_x4(a[mt], sA + (uint32_t)(row*40 + k16 + ((lane>>4)<<3))*2);
        }
        uint32_t bfr[4][4];
        #pragma unroll
        for (int np = 0; np < 4; ++np){
            int row = n_off + np*16 + (lane & 7) + ((lane>>4)&1)*8;
            ldsm_x4(bfr[np], sB + (uint32_t)(row*40 + k16 + (((lane>>3)&1)<<3))*2);
        }
        #pragma unroll
        for (int mt = 0; mt < 4; ++mt)
            #pragma unroll
            for (int nt = 0; nt < 8; ++nt)
                mma16816(c[mt][nt], a[mt], &bfr[nt>>1][(nt&1)*2]);
    }
}

// ---------------- preprocessing kernels ------------------------------------
__global__ void k_bits(const int* __restrict__ adj, const int* __restrict__ mask){
    int warp = threadIdx.x >> 5, lane = threadIdx.x & 31;
    int r = blockIdx.x * 8 + warp;
    int b = (r / N_) % B_;
    int i = r % N_;
    int mi = mask[b*N_ + i];
    const int* arow = adj + (size_t)r * N_;
    unsigned keep = 0;
    #pragma unroll
    for (int c = 0; c < 8; c++){
        int j = c*32 + lane;
        int bit = mi && mask[b*N_ + j] && arow[j] && (j != i);
        unsigned wrd = __ballot_sync(0xffffffffu, bit != 0);
        if (lane == c) keep = wrd;
    }
    if (lane < 8) g_bits[(size_t)r*8 + lane] = keep;
}
__global__ void k_neigh(){
    int t = blockIdx.x*blockDim.x + threadIdx.x;
    int b = t / N_;
    int s = 0;
    for (int e = 0; e < E_; e++){
        const unsigned* row = g_bits + (size_t)((e*B_+b)*N_ + (t % N_))*8;
        #pragma unroll
        for (int c = 0; c < 8; c++) s += __popc(row[c]);
    }
    float n = (float)s; if (n < 1.f) n = 1.f;
    g_invneigh[t] = 1.f / n;
}
__global__ void k_bstack(const float* __restrict__ We, const float* __restrict__ Ws){
    int idx = blockIdx.x*256 + threadIdx.x;
    if (idx >= D_*KT_) return;
    int d = idx / KT_, kk = idx % KT_;
    float w;
    if (kk < KX_){ int e = kk / D_, k2 = kk % D_; w = We[((size_t)e*D_ + d)*D_ + k2]; }
    else w = Ws[(size_t)d*D_ + (kk - KX_)];
    fp16 h = __float2half(w);
    fp16 l = __float2half(w - __half2float(h));
    size_t base = (size_t)d*KS_;
    g_Bstack[base + kk]        = h;   // pairs with Xhi
    g_Bstack[base + KT_ + kk]  = h;   // pairs with Xlo
    g_Bstack[base + 2*KT_ + kk]= l;   // pairs with Xhi
}

// ---------------- per-iteration elementwise kernels -------------------------
__global__ void k_w(const float* __restrict__ node0, int useScratch,
                    const float* __restrict__ Wnw, const float* __restrict__ bnw,
                    float* __restrict__ woutBase, int it){
    int warp = threadIdx.x >> 5, lane = threadIdx.x & 31;
    int r = blockIdx.x*8 + warp;
    const float* node = useScratch ? g_nodeA : node0;
    const float4* nr = (const float4*)(node + (size_t)r*D_);
    const float4* wr = (const float4*)Wnw;
    float s = 0.f;
    #pragma unroll
    for (int c = 0; c < 4; c++){
        float4 a = nr[c*32 + lane], w = wr[c*32 + lane];
        s += a.x*w.x + a.y*w.y + a.z*w.z + a.w*w.w;
    }
    #pragma unroll
    for (int o = 16; o; o >>= 1) s += __shfl_down_sync(0xffffffffu, s, o);
    if (lane == 0){
        float z = s + bnw[0];
        float w = 1.f / (1.f + expf(-z));
        g_w[r] = w;
        int b = r / N_, n = r % N_;
        woutBase[(size_t)b*(2*N_) + it*N_ + n] = w;
    }
}
__global__ void k_split(const float* __restrict__ node0){
    int idx = blockIdx.x*256 + threadIdx.x;
    float v = node0[idx];
    fp16 h = __float2half(v);
    g_nhi[idx] = h;
    g_nlo[idx] = __float2half(v - __half2float(h));
}
__global__ void k_zt(const float* __restrict__ node0, int useScratch){
    __shared__ float s[32][33];
    const float* node = useScratch ? g_nodeA : node0;
    int b = blockIdx.z, d0 = blockIdx.x*32, j0 = blockIdx.y*32;
    int tx = threadIdx.x, ty = threadIdx.y;
    int j = j0 + ty;
    s[ty][tx] = node[((size_t)b*N_ + j)*D_ + d0 + tx] * g_w[b*N_ + j];
    __syncthreads();
    float v = s[tx][ty];
    fp16 h = __float2half(v);
    fp16 l = __float2half(v - __half2float(h));
    size_t base = ((size_t)b*D_ + d0 + ty) * (size_t)(2*N_);
    g_Zt[base + j0 + tx]      = h;
    g_Zt[base + N_ + j0 + tx] = l;
}

// ---------------- stage A GEMM: X = (G @ Zt) * inv_neigh -> Xhi/Xlo ---------
// CTA tile 128x256; A(=G fp16 0/1) expanded from g_bits in-kernel; K=512.
__global__ void __launch_bounds__(256, 1) k_gemmA(){
    extern __shared__ char dsm[];
    uint32_t sbase = smem_u32(dsm);
    int tid = threadIdx.x, wid = tid >> 5, lane = tid & 31;
    int dBase = blockIdx.x * 256;           // 0 or 256
    int y = blockIdx.y;                     // be*2 + mhalf
    int mhalf = y & 1; int be = y >> 1;
    int e = be % E_, b = be / E_;
    int m_off = (wid >> 2) * 64;
    int n_off = (wid & 3) * 64;

    const fp16* Zbase = g_Zt + ((size_t)b*D_ + dBase) * (size_t)(2*N_);
    const unsigned* bitbase = g_bits + (size_t)(((size_t)e*B_ + b)*N_ + mhalf*128)*8;

    int rA = tid >> 1, hsel = tid & 1;      // A expand: row, 16-bit half

    auto loadB = [&](int itk, int s){
        uint32_t sB = sbase + s*STG_BYTES + OFF_B;
        const fp16* src = Zbase + (size_t)tid*(2*N_) + itk*32;
        uint32_t d0 = sB + (uint32_t)(tid*40)*2;
        cpa16(d0,      src);
        cpa16(d0 + 16, src + 8);
        cpa16(d0 + 32, src + 16);
        cpa16(d0 + 48, src + 24);
        CP_COMMIT();
    };
    auto expandA = [&](int itk, int s){
        unsigned w32 = bitbase[(size_t)rA*8 + (itk & 7)];
        unsigned bits = (w32 >> (hsel*16)) & 0xFFFFu;
        uint32_t u[8];
        #pragma unroll
        for (int q = 0; q < 8; ++q){
            u[q] = ((bits >> (2*q)) & 1u ? 0x3C00u : 0u)
                 | ((bits >> (2*q+1)) & 1u ? 0x3C000000u : 0u);
        }
        char* dst = dsm + s*STG_BYTES + (rA*40 + hsel*16)*2;
        *(uint4*)(dst)      = make_uint4(u[0],u[1],u[2],u[3]);
        *(uint4*)(dst + 16) = make_uint4(u[4],u[5],u[6],u[7]);
    };

    float c[4][8][4];
    #pragma unroll
    for (int i = 0; i < 4; ++i)
        #pragma unroll
        for (int j = 0; j < 8; ++j)
            #pragma unroll
            for (int q = 0; q < 4; ++q) c[i][j][q] = 0.f;

    expandA(0, 0);
    loadB(0, 0); loadB(1, 1); loadB(2, 2);
    for (int it = 0; it < KI_A; ++it){
        CP_WAIT2();
        __syncthreads();
        if (it + 1 < KI_A) expandA(it + 1, (it + 1) & 3);
        if (it + 3 < KI_A) loadB(it + 3, (it + 3) & 3); else CP_COMMIT();
        int s = it & 3;
        warp_compute(sbase + s*STG_BYTES, sbase + s*STG_BYTES + OFF_B,
                     m_off, n_off, c, lane);
    }

    // epilogue: * inv_neigh, split fp16 hi/lo
    #pragma unroll
    for (int mt = 0; mt < 4; ++mt){
        int i1 = mhalf*128 + m_off + mt*16 + (lane >> 2);
        int r1 = b*N_ + i1;
        float inv1 = g_invneigh[r1];
        float inv2 = g_invneigh[r1 + 8];
        #pragma unroll
        for (int nt = 0; nt < 8; ++nt){
            int col = e*D_ + dBase + n_off + nt*8 + (lane & 3)*2;
            float x0 = c[mt][nt][0]*inv1, x1 = c[mt][nt][1]*inv1;
            float x2 = c[mt][nt][2]*inv2, x3 = c[mt][nt][3]*inv2;
            fp16 h0=__float2half(x0), h1=__float2half(x1);
            fp16 h2=__float2half(x2), h3=__float2half(x3);
            fp16 l0=__float2half(x0-__half2float(h0));
            fp16 l1=__float2half(x1-__half2float(h1));
            fp16 l2=__float2half(x2-__half2float(h2));
            fp16 l3=__float2half(x3-__half2float(h3));
            uint32_t hw0=(uint32_t)__half_as_ushort(h0)|((uint32_t)__half_as_ushort(h1)<<16);
            uint32_t hw1=(uint32_t)__half_as_ushort(h2)|((uint32_t)__half_as_ushort(h3)<<16);
            uint32_t lw0=(uint32_t)__half_as_ushort(l0)|((uint32_t)__half_as_ushort(l1)<<16);
            uint32_t lw1=(uint32_t)__half_as_ushort(l2)|((uint32_t)__half_as_ushort(l3)<<16);
            *(uint32_t*)(g_Xhi + (size_t)r1*KX_ + col)     = hw0;
            *(uint32_t*)(g_Xhi + (size_t)(r1+8)*KX_ + col) = hw1;
            *(uint32_t*)(g_Xlo + (size_t)r1*KX_ + col)     = lw0;
            *(uint32_t*)(g_Xlo + (size_t)(r1+8)*KX_ + col) = lw1;
        }
    }
}

// ---------------- stage B GEMM: out = relu([Xhi|Xlo|Xhi] @ Bstack + bias) ---
// CTA tile 128x256, K=16896 (3 parts x 5632).
__global__ void __launch_bounds__(256, 1) k_gemmB(const float* __restrict__ bself,
                                                  float* __restrict__ out0,
                                                  int srcSel, int outMode){
    extern __shared__ char dsm[];
    uint32_t sbase = smem_u32(dsm);
    int tid = threadIdx.x, wid = tid >> 5, lane = tid & 31;
    int dBase = blockIdx.x * 256;
    int mBase = blockIdx.y * 128;
    int m_off = (wid >> 2) * 64;
    int n_off = (wid & 3) * 64;

    const fp16* NHI = srcSel ? g_nhi2 : g_nhi;
    const fp16* NLO = srcSel ? g_nlo2 : g_nlo;
    int rA = tid >> 1, cA = (tid & 1)*2;

    auto load = [&](int itk, int s){
        uint32_t sA = sbase + s*STG_BYTES;
        uint32_t sB = sA + OFF_B;
        int part = itk / 176;
        int rr = (itk - part*176) * 32;
        const fp16* Ab; size_t ap;
        if (rr < KX_){ Ab = (part == 1 ? g_Xlo : g_Xhi) + (size_t)mBase*KX_ + rr; ap = KX_; }
        else         { Ab = (part == 1 ? NLO : NHI) + (size_t)mBase*D_ + (rr - KX_); ap = D_; }
        uint32_t dA = sA + (uint32_t)(rA*40 + cA*8)*2;
        cpa16(dA,      Ab + (size_t)rA*ap + cA*8);
        cpa16(dA + 16, Ab + (size_t)rA*ap + cA*8 + 8);
        const fp16* Bb = g_Bstack + (size_t)(dBase + tid)*KS_ + (size_t)itk*32;
        uint32_t dB = sB + (uint32_t)(tid*40)*2;
        cpa16(dB,      Bb);
        cpa16(dB + 16, Bb + 8);
        cpa16(dB + 32, Bb + 16);
        cpa16(dB + 48, Bb + 24);
        CP_COMMIT();
    };

    float c[4][8][4];
    #pragma unroll
    for (int i = 0; i < 4; ++i)
        #pragma unroll
        for (int j = 0; j < 8; ++j)
            #pragma unroll
            for (int q = 0; q < 4; ++q) c[i][j][q] = 0.f;

    load(0, 0); load(1, 1); load(2, 2);
    for (int it = 0; it < KI_B; ++it){
        CP_WAIT2();
        __syncthreads();
        if (it + 3 < KI_B) load(it + 3, (it + 3) & 3); else CP_COMMIT();
        int s = it & 3;
        warp_compute(sbase + s*STG_BYTES, sbase + s*STG_BYTES + OFF_B,
                     m_off, n_off, c, lane);
    }

    #pragma unroll
    for (int mt = 0; mt < 4; ++mt){
        int m1 = mBase + m_off + mt*16 + (lane >> 2);
        #pragma unroll
        for (int nt = 0; nt < 8; ++nt){
            int n = dBase + n_off + nt*8 + (lane & 3)*2;
            float bi0 = __ldg(bself + n), bi1 = __ldg(bself + n + 1);
            float v0 = c[mt][nt][0] + bi0, v1 = c[mt][nt][1] + bi1;
            float v2 = c[mt][nt][2] + bi0, v3 = c[mt][nt][3] + bi1;
            v0 = v0 > 0.f ? v0 : 0.f; v1 = v1 > 0.f ? v1 : 0.f;
            v2 = v2 > 0.f ? v2 : 0.f; v3 = v3 > 0.f ? v3 : 0.f;
            if (outMode){
                // intermediate: write fp32 scratch + fp16 hi/lo for next iter
                *(float2*)(g_nodeA + (size_t)m1*D_ + n)     = make_float2(v0, v1);
                *(float2*)(g_nodeA + (size_t)(m1+8)*D_ + n) = make_float2(v2, v3);
                fp16 h0=__float2half(v0), h1=__float2half(v1);
                fp16 h2=__float2half(v2), h3=__float2half(v3);
                fp16 l0=__float2half(v0-__half2float(h0));
                fp16 l1=__float2half(v1-__half2float(h1));
                fp16 l2=__float2half(v2-__half2float(h2));
                fp16 l3=__float2half(v3-__half2float(h3));
                *(uint32_t*)(g_nhi2 + (size_t)m1*D_ + n)     = (uint32_t)__half_as_ushort(h0)|((uint32_t)__half_as_ushort(h1)<<16);
                *(uint32_t*)(g_nhi2 + (size_t)(m1+8)*D_ + n) = (uint32_t)__half_as_ushort(h2)|((uint32_t)__half_as_ushort(h3)<<16);
                *(uint32_t*)(g_nlo2 + (size_t)m1*D_ + n)     = (uint32_t)__half_as_ushort(l0)|((uint32_t)__half_as_ushort(l1)<<16);
                *(uint32_t*)(g_nlo2 + (size_t)(m1+8)*D_ + n) = (uint32_t)__half_as_ushort(l2)|((uint32_t)__half_as_ushort(l3)<<16);
            } else {
                *(float2*)(out0 + (size_t)m1*D_ + n)     = make_float2(v0, v1);
                *(float2*)(out0 + (size_t)(m1+8)*D_ + n) = make_float2(v2, v3);
            }
        }
    }
}

// ---------------- launch ----------------------------------------------------
extern "C" void kernel_launch(void* const* d_in, const int* in_sizes, int n_in,
                              void* d_out, int out_size){
    const float* node  = (const float*)d_in[0];
    const float* Wnw   = (const float*)d_in[1];
    const float* bnw   = (const float*)d_in[2];
    const float* Wself = (const float*)d_in[3];
    const float* bself = (const float*)d_in[4];
    const float* Wedge = (const float*)d_in[5];
    const int*   mask  = (const int*)d_in[6];
    const int*   adj   = (const int*)d_in[7];

    float* out  = (float*)d_out;
    float* outW = out + (size_t)M_*D_;

    cudaFuncSetAttribute(k_gemmA, cudaFuncAttributeMaxDynamicSharedMemorySize, SMEM_DYN);
    cudaFuncSetAttribute(k_gemmB, cudaFuncAttributeMaxDynamicSharedMemorySize, SMEM_DYN);

    // iteration-invariant preprocessing
    k_bstack<<<(D_*KT_ + 255)/256, 256>>>(Wedge, Wself);
    k_bits  <<<(E_*B_*N_)/8, 256>>>(adj, mask);
    k_neigh <<<M_/256, 256>>>();

    // ---- iteration 0: node -> g_nodeA (+ nhi2/nlo2) ----
    k_w    <<<M_/8, 256>>>(node, 0, Wnw, bnw, outW, 0);
    k_split<<<(M_*D_)/256, 256>>>(node);
    k_zt   <<<dim3(16, 8, B_), dim3(32, 32)>>>(node, 0);
    k_gemmA<<<dim3(2, B_*E_*2), 256, SMEM_DYN>>>();
    k_gemmB<<<dim3(2, M_/128), 256, SMEM_DYN>>>(bself, out, 0, 1);

    // ---- iteration 1: g_nodeA -> d_out ----
    k_w    <<<M_/8, 256>>>(node, 1, Wnw, bnw, outW, 1);
    k_zt   <<<dim3(16, 8, B_), dim3(32, 32)>>>(node, 1);
    k_gemmA<<<dim3(2, B_*E_*2), 256, SMEM_DYN>>>();
    k_gemmB<<<dim3(2, M_/128), 256, SMEM_DYN>>>(bself, out, 1, 0);
}

// round 5
// speedup vs baseline: 2.0443x; 1.3268x over previous
#include <cuda_runtime.h>
#include <cuda_fp16.h>
#include <math.h>
#include <stdint.h>

// ---------------- problem constants ----------------
#define B_  64
#define N_  256
#define D_  512
#define E_  10
#define M_  (B_*N_)        // 16384
#define KX_ (E_*D_)        // 5120
#define KT_ (KX_+D_)       // 5632
#define KS2_ (2*KT_)       // 11264 (fp16 2-term stacked K for stage B)
#define KI_B (KS2_/32)     // 352 k-iters (stage B)
#define KI_A 16            // k-iters (stage A, K=512)

typedef __half fp16;

// ---------------- device scratch (static; no runtime allocation) ----------
__device__ unsigned g_bits[(size_t)E_*B_*N_*8];      // binary graphs bitmask
__device__ float    g_invneigh[M_];
__device__ float    g_w[M_];
__device__ float    g_nodeA[(size_t)M_*D_];          // fp32 node ping buffer
__device__ fp16     g_Bstack[(size_t)D_*KT_];        // [d][kk] = Whi (fp16 RN of W)
__device__ fp16     g_Zt[(size_t)B_*D_*2*N_];        // [b][d][k] k<256:hi(j) else lo
__device__ fp16     g_Xhi[(size_t)M_*KX_];
__device__ fp16     g_Xlo[(size_t)M_*KX_];
__device__ fp16     g_nhi[(size_t)M_*D_],  g_nlo[(size_t)M_*D_];
__device__ fp16     g_nhi2[(size_t)M_*D_], g_nlo2[(size_t)M_*D_];

// ---------------- PTX helpers ----------------------------------------------
__device__ __forceinline__ uint32_t smem_u32(const void* p){
    uint32_t a; asm("{ .reg .u64 t; cvta.to.shared.u64 t, %1; cvt.u32.u64 %0, t; }"
                    : "=r"(a) : "l"(p)); return a;
}
__device__ __forceinline__ void cpa16(uint32_t dst, const void* src){
    asm volatile("cp.async.cg.shared.global [%0], [%1], 16;" :: "r"(dst), "l"(src));
}
#define CP_COMMIT() asm volatile("cp.async.commit_group;" ::: "memory")
#define CP_WAIT2()  asm volatile("cp.async.wait_group 2;" ::: "memory")

__device__ __forceinline__ void ldsm_x4(uint32_t* r, uint32_t addr){
    asm volatile("ldmatrix.sync.aligned.m8n8.x4.shared.b16 {%0,%1,%2,%3}, [%4];"
        : "=r"(r[0]),"=r"(r[1]),"=r"(r[2]),"=r"(r[3]) : "r"(addr));
}
__device__ __forceinline__ void mma16816(float* c, const uint32_t* a, const uint32_t* b){
    asm volatile("mma.sync.aligned.m16n8k16.row.col.f32.f16.f16.f32 "
        "{%0,%1,%2,%3},{%4,%5,%6,%7},{%8,%9},{%0,%1,%2,%3};"
        : "+f"(c[0]),"+f"(c[1]),"+f"(c[2]),"+f"(c[3])
        : "r"(a[0]),"r"(a[1]),"r"(a[2]),"r"(a[3]), "r"(b[0]),"r"(b[1]));
}

// smem: 4 stages; per stage As[128][40] + Bs[256][40] fp16 (80B pitch ->
// 8 consecutive rows hit distinct bank groups, conflict-free ldmatrix)
#define STG_BYTES 30720
#define OFF_B     10240
#define SMEM_DYN  (4*STG_BYTES)

// warp tile 64x64 (8 warps: 2 m x 4 n over 128x256 CTA tile)
__device__ __forceinline__ void warp_compute(uint32_t sA, uint32_t sB,
                                             int m_off, int n_off,
                                             float c[4][8][4], int lane){
    #pragma unroll
    for (int kh = 0; kh < 2; ++kh){
        int k16 = kh*16;
        uint32_t a[4][4];
        #pragma unroll
        for (int mt = 0; mt < 4; ++mt){
            int row = m_off + mt*16 + (lane & 15);
            ldsm_x4(a[mt], sA + (uint32_t)(row*40 + k16 + ((lane>>4)<<3))*2);
        }
        uint32_t bfr[4][4];
        #pragma unroll
        for (int np = 0; np < 4; ++np){
            int row = n_off + np*16 + (lane & 7) + ((lane>>4)&1)*8;
            ldsm_x4(bfr[np], sB + (uint32_t)(row*40 + k16 + (((lane>>3)&1)<<3))*2);
        }
        #pragma unroll
        for (int mt = 0; mt < 4; ++mt)
            #pragma unroll
            for (int nt = 0; nt < 8; ++nt)
                mma16816(c[mt][nt], a[mt], &bfr[nt>>1][(nt&1)*2]);
    }
}

// ---------------- preprocessing kernels ------------------------------------
__global__ void k_bits(const int* __restrict__ adj, const int* __restrict__ mask){
    int warp = threadIdx.x >> 5, lane = threadIdx.x & 31;
    int r = blockIdx.x * 8 + warp;
    int b = (r / N_) % B_;
    int i = r % N_;
    int mi = mask[b*N_ + i];
    const int* arow = adj + (size_t)r * N_;
    unsigned keep = 0;
    #pragma unroll
    for (int c = 0; c < 8; c++){
        int j = c*32 + lane;
        int bit = mi && mask[b*N_ + j] && arow[j] && (j != i);
        unsigned wrd = __ballot_sync(0xffffffffu, bit != 0);
        if (lane == c) keep = wrd;
    }
    if (lane < 8) g_bits[(size_t)r*8 + lane] = keep;
}
__global__ void k_neigh(){
    int t = blockIdx.x*blockDim.x + threadIdx.x;
    int b = t / N_;
    int s = 0;
    for (int e = 0; e < E_; e++){
        const unsigned* row = g_bits + (size_t)((e*B_+b)*N_ + (t % N_))*8;
        #pragma unroll
        for (int c = 0; c < 8; c++) s += __popc(row[c]);
    }
    float n = (float)s; if (n < 1.f) n = 1.f;
    g_invneigh[t] = 1.f / n;
}
__global__ void k_bstack(const float* __restrict__ We, const float* __restrict__ Ws){
    int idx = blockIdx.x*256 + threadIdx.x;
    if (idx >= D_*KT_) return;
    int d = idx / KT_, kk = idx % KT_;
    float w;
    if (kk < KX_){ int e = kk / D_, k2 = kk % D_; w = We[((size_t)e*D_ + d)*D_ + k2]; }
    else w = Ws[(size_t)d*D_ + (kk - KX_)];
    g_Bstack[(size_t)d*KT_ + kk] = __float2half(w);
}

// ---------------- per-iteration elementwise kernels -------------------------
__global__ void k_w(const float* __restrict__ node0, int useScratch,
                    const float* __restrict__ Wnw, const float* __restrict__ bnw,
                    float* __restrict__ woutBase, int it){
    int warp = threadIdx.x >> 5, lane = threadIdx.x & 31;
    int r = blockIdx.x*8 + warp;
    const float* node = useScratch ? g_nodeA : node0;
    const float4* nr = (const float4*)(node + (size_t)r*D_);
    const float4* wr = (const float4*)Wnw;
    float s = 0.f;
    #pragma unroll
    for (int c = 0; c < 4; c++){
        float4 a = nr[c*32 + lane], w = wr[c*32 + lane];
        s += a.x*w.x + a.y*w.y + a.z*w.z + a.w*w.w;
    }
    #pragma unroll
    for (int o = 16; o; o >>= 1) s += __shfl_down_sync(0xffffffffu, s, o);
    if (lane == 0){
        float z = s + bnw[0];
        float w = 1.f / (1.f + expf(-z));
        g_w[r] = w;
        int b = r / N_, n = r % N_;
        woutBase[(size_t)b*(2*N_) + it*N_ + n] = w;
    }
}
// transpose w*node -> Zt (fp16 hi/lo, K-stacked); iter 0 also emits nhi/nlo
__global__ void k_zt(const float* __restrict__ node0, int useScratch){
    __shared__ float s[32][33];
    const float* node = useScratch ? g_nodeA : node0;
    int b = blockIdx.z, d0 = blockIdx.x*32, j0 = blockIdx.y*32;
    int tx = threadIdx.x, ty = threadIdx.y;
    int j = j0 + ty;
    size_t gidx = ((size_t)b*N_ + j)*D_ + d0 + tx;
    float raw = node[gidx];
    if (!useScratch){
        fp16 h = __float2half(raw);
        g_nhi[gidx] = h;
        g_nlo[gidx] = __float2half(raw - __half2float(h));
    }
    s[ty][tx] = raw * g_w[b*N_ + j];
    __syncthreads();
    float v = s[tx][ty];
    fp16 h = __float2half(v);
    fp16 l = __float2half(v - __half2float(h));
    size_t base = ((size_t)b*D_ + d0 + ty) * (size_t)(2*N_);
    g_Zt[base + j0 + tx]      = h;
    g_Zt[base + N_ + j0 + tx] = l;
}

// ---------------- stage A GEMM: X = (G @ Zt) * inv_neigh -> Xhi/Xlo ---------
// CTA tile 128x256; A(=G fp16 0/1) expanded from g_bits in-kernel; K=512.
__global__ void __launch_bounds__(256, 1) k_gemmA(){
    extern __shared__ char dsm[];
    uint32_t sbase = smem_u32(dsm);
    int tid = threadIdx.x, wid = tid >> 5, lane = tid & 31;
    int dBase = blockIdx.x * 256;           // 0 or 256
    int y = blockIdx.y;                     // be*2 + mhalf
    int mhalf = y & 1; int be = y >> 1;
    int e = be % E_, b = be / E_;
    int m_off = (wid >> 2) * 64;
    int n_off = (wid & 3) * 64;

    const fp16* Zbase = g_Zt + ((size_t)b*D_ + dBase) * (size_t)(2*N_);
    const unsigned* bitbase = g_bits + (size_t)(((size_t)e*B_ + b)*N_ + mhalf*128)*8;

    int rA = tid >> 1, hsel = tid & 1;      // A expand: row, 16-bit half

    auto loadB = [&](int itk, int s){
        uint32_t sB = sbase + s*STG_BYTES + OFF_B;
        const fp16* src = Zbase + (size_t)tid*(2*N_) + itk*32;
        uint32_t d0 = sB + (uint32_t)(tid*40)*2;
        cpa16(d0,      src);
        cpa16(d0 + 16, src + 8);
        cpa16(d0 + 32, src + 16);
        cpa16(d0 + 48, src + 24);
        CP_COMMIT();
    };
    auto expandA = [&](int itk, int s){
        unsigned w32 = bitbase[(size_t)rA*8 + (itk & 7)];
        unsigned bits = (w32 >> (hsel*16)) & 0xFFFFu;
        uint32_t u[8];
        #pragma unroll
        for (int q = 0; q < 8; ++q){
            u[q] = ((bits >> (2*q)) & 1u ? 0x3C00u : 0u)
                 | ((bits >> (2*q+1)) & 1u ? 0x3C000000u : 0u);
        }
        char* dst = dsm + s*STG_BYTES + (rA*40 + hsel*16)*2;
        *(uint4*)(dst)      = make_uint4(u[0],u[1],u[2],u[3]);
        *(uint4*)(dst + 16) = make_uint4(u[4],u[5],u[6],u[7]);
    };

    float c[4][8][4];
    #pragma unroll
    for (int i = 0; i < 4; ++i)
        #pragma unroll
        for (int j = 0; j < 8; ++j)
            #pragma unroll
            for (int q = 0; q < 4; ++q) c[i][j][q] = 0.f;

    expandA(0, 0);
    loadB(0, 0); loadB(1, 1); loadB(2, 2);
    for (int it = 0; it < KI_A; ++it){
        CP_WAIT2();
        __syncthreads();
        if (it + 1 < KI_A) expandA(it + 1, (it + 1) & 3);
        if (it + 3 < KI_A) loadB(it + 3, (it + 3) & 3); else CP_COMMIT();
        int s = it & 3;
        warp_compute(sbase + s*STG_BYTES, sbase + s*STG_BYTES + OFF_B,
                     m_off, n_off, c, lane);
    }

    // epilogue: * inv_neigh, split fp16 hi/lo
    #pragma unroll
    for (int mt = 0; mt < 4; ++mt){
        int i1 = mhalf*128 + m_off + mt*16 + (lane >> 2);
        int r1 = b*N_ + i1;
        float inv1 = g_invneigh[r1];
        float inv2 = g_invneigh[r1 + 8];
        #pragma unroll
        for (int nt = 0; nt < 8; ++nt){
            int col = e*D_ + dBase + n_off + nt*8 + (lane & 3)*2;
            float x0 = c[mt][nt][0]*inv1, x1 = c[mt][nt][1]*inv1;
            float x2 = c[mt][nt][2]*inv2, x3 = c[mt][nt][3]*inv2;
            fp16 h0=__float2half(x0), h1=__float2half(x1);
            fp16 h2=__float2half(x2), h3=__float2half(x3);
            fp16 l0=__float2half(x0-__half2float(h0));
            fp16 l1=__float2half(x1-__half2float(h1));
            fp16 l2=__float2half(x2-__half2float(h2));
            fp16 l3=__float2half(x3-__half2float(h3));
            uint32_t hw0=(uint32_t)__half_as_ushort(h0)|((uint32_t)__half_as_ushort(h1)<<16);
            uint32_t hw1=(uint32_t)__half_as_ushort(h2)|((uint32_t)__half_as_ushort(h3)<<16);
            uint32_t lw0=(uint32_t)__half_as_ushort(l0)|((uint32_t)__half_as_ushort(l1)<<16);
            uint32_t lw1=(uint32_t)__half_as_ushort(l2)|((uint32_t)__half_as_ushort(l3)<<16);
            *(uint32_t*)(g_Xhi + (size_t)r1*KX_ + col)     = hw0;
            *(uint32_t*)(g_Xhi + (size_t)(r1+8)*KX_ + col) = hw1;
            *(uint32_t*)(g_Xlo + (size_t)r1*KX_ + col)     = lw0;
            *(uint32_t*)(g_Xlo + (size_t)(r1+8)*KX_ + col) = lw1;
        }
    }
}

// ---------------- stage B GEMM: out = relu([Xhi|Xlo] @ [Whi;Whi] + bias) ----
// CTA tile 128x256, K=11264 (2 parts x 5632), B-side streams Whi twice.
__global__ void __launch_bounds__(256, 1) k_gemmB(const float* __restrict__ bself,
                                                  float* __restrict__ out0,
                                                  int srcSel, int outMode){
    extern __shared__ char dsm[];
    uint32_t sbase = smem_u32(dsm);
    int tid = threadIdx.x, wid = tid >> 5, lane = tid & 31;
    int dBase = blockIdx.x * 256;
    int mBase = blockIdx.y * 128;
    int m_off = (wid >> 2) * 64;
    int n_off = (wid & 3) * 64;

    const fp16* NHI = srcSel ? g_nhi2 : g_nhi;
    const fp16* NLO = srcSel ? g_nlo2 : g_nlo;
    int rA = tid >> 1, cA = (tid & 1)*2;

    auto load = [&](int itk, int s){
        uint32_t sA = sbase + s*STG_BYTES;
        uint32_t sB = sA + OFF_B;
        int part = itk / 176;               // 0: hi inputs, 1: lo inputs
        int rr = (itk - part*176) * 32;
        const fp16* Ab; size_t ap;
        if (rr < KX_){ Ab = (part ? g_Xlo : g_Xhi) + (size_t)mBase*KX_ + rr; ap = KX_; }
        else         { Ab = (part ? NLO : NHI) + (size_t)mBase*D_ + (rr - KX_); ap = D_; }
        uint32_t dA = sA + (uint32_t)(rA*40 + cA*8)*2;
        cpa16(dA,      Ab + (size_t)rA*ap + cA*8);
        cpa16(dA + 16, Ab + (size_t)rA*ap + cA*8 + 8);
        const fp16* Bb = g_Bstack + (size_t)(dBase + tid)*KT_ + rr;  // Whi both parts
        uint32_t dB = sB + (uint32_t)(tid*40)*2;
        cpa16(dB,      Bb);
        cpa16(dB + 16, Bb + 8);
        cpa16(dB + 32, Bb + 16);
        cpa16(dB + 48, Bb + 24);
        CP_COMMIT();
    };

    float c[4][8][4];
    #pragma unroll
    for (int i = 0; i < 4; ++i)
        #pragma unroll
        for (int j = 0; j < 8; ++j)
            #pragma unroll
            for (int q = 0; q < 4; ++q) c[i][j][q] = 0.f;

    load(0, 0); load(1, 1); load(2, 2);
    for (int it = 0; it < KI_B; ++it){
        CP_WAIT2();
        __syncthreads();
        if (it + 3 < KI_B) load(it + 3, (it + 3) & 3); else CP_COMMIT();
        int s = it & 3;
        warp_compute(sbase + s*STG_BYTES, sbase + s*STG_BYTES + OFF_B,
                     m_off, n_off, c, lane);
    }

    #pragma unroll
    for (int mt = 0; mt < 4; ++mt){
        int m1 = mBase + m_off + mt*16 + (lane >> 2);
        #pragma unroll
        for (int nt = 0; nt < 8; ++nt){
            int n = dBase + n_off + nt*8 + (lane & 3)*2;
            float bi0 = __ldg(bself + n), bi1 = __ldg(bself + n + 1);
            float v0 = c[mt][nt][0] + bi0, v1 = c[mt][nt][1] + bi1;
            float v2 = c[mt][nt][2] + bi0, v3 = c[mt][nt][3] + bi1;
            v0 = v0 > 0.f ? v0 : 0.f; v1 = v1 > 0.f ? v1 : 0.f;
            v2 = v2 > 0.f ? v2 : 0.f; v3 = v3 > 0.f ? v3 : 0.f;
            if (outMode){
                // intermediate: write fp32 scratch + fp16 hi/lo for next iter
                *(float2*)(g_nodeA + (size_t)m1*D_ + n)     = make_float2(v0, v1);
                *(float2*)(g_nodeA + (size_t)(m1+8)*D_ + n) = make_float2(v2, v3);
                fp16 h0=__float2half(v0), h1=__float2half(v1);
                fp16 h2=__float2half(v2), h3=__float2half(v3);
                fp16 l0=__float2half(v0-__half2float(h0));
                fp16 l1=__float2half(v1-__half2float(h1));
                fp16 l2=__float2half(v2-__half2float(h2));
                fp16 l3=__float2half(v3-__half2float(h3));
                *(uint32_t*)(g_nhi2 + (size_t)m1*D_ + n)     = (uint32_t)__half_as_ushort(h0)|((uint32_t)__half_as_ushort(h1)<<16);
                *(uint32_t*)(g_nhi2 + (size_t)(m1+8)*D_ + n) = (uint32_t)__half_as_ushort(h2)|((uint32_t)__half_as_ushort(h3)<<16);
                *(uint32_t*)(g_nlo2 + (size_t)m1*D_ + n)     = (uint32_t)__half_as_ushort(l0)|((uint32_t)__half_as_ushort(l1)<<16);
                *(uint32_t*)(g_nlo2 + (size_t)(m1+8)*D_ + n) = (uint32_t)__half_as_ushort(l2)|((uint32_t)__half_as_ushort(l3)<<16);
            } else {
                *(float2*)(out0 + (size_t)m1*D_ + n)     = make_float2(v0, v1);
                *(float2*)(out0 + (size_t)(m1+8)*D_ + n) = make_float2(v2, v3);
            }
        }
    }
}

// ---------------- launch ----------------------------------------------------
extern "C" void kernel_launch(void* const* d_in, const int* in_sizes, int n_in,
                              void* d_out, int out_size){
    const float* node  = (const float*)d_in[0];
    const float* Wnw   = (const float*)d_in[1];
    const float* bnw   = (const float*)d_in[2];
    const float* Wself = (const float*)d_in[3];
    const float* bself = (const float*)d_in[4];
    const float* Wedge = (const float*)d_in[5];
    const int*   mask  = (const int*)d_in[6];
    const int*   adj   = (const int*)d_in[7];

    float* out  = (float*)d_out;
    float* outW = out + (size_t)M_*D_;

    cudaFuncSetAttribute(k_gemmA, cudaFuncAttributeMaxDynamicSharedMemorySize, SMEM_DYN);
    cudaFuncSetAttribute(k_gemmB, cudaFuncAttributeMaxDynamicSharedMemorySize, SMEM_DYN);

    // iteration-invariant preprocessing
    k_bstack<<<(D_*KT_ + 255)/256, 256>>>(Wedge, Wself);
    k_bits  <<<(E_*B_*N_)/8, 256>>>(adj, mask);
    k_neigh <<<M_/256, 256>>>();

    // ---- iteration 0: node -> g_nodeA (+ nhi2/nlo2) ----
    k_w    <<<M_/8, 256>>>(node, 0, Wnw, bnw, outW, 0);
    k_zt   <<<dim3(16, 8, B_), dim3(32, 32)>>>(node, 0);
    k_gemmA<<<dim3(2, B_*E_*2), 256, SMEM_DYN>>>();
    k_gemmB<<<dim3(2, M_/128), 256, SMEM_DYN>>>(bself, out, 0, 1);

    // ---- iteration 1: g_nodeA -> d_out ----
    k_w    <<<M_/8, 256>>>(node, 1, Wnw, bnw, outW, 1);
    k_zt   <<<dim3(16, 8, B_), dim3(32, 32)>>>(node, 1);
    k_gemmA<<<dim3(2, B_*E_*2), 256, SMEM_DYN>>>();
    k_gemmB<<<dim3(2, M_/128), 256, SMEM_DYN>>>(bself, out, 1, 0);
}

// round 6
// speedup vs baseline: 3.5134x; 1.7187x over previous
#include <cuda_runtime.h>
#include <cuda_fp16.h>
#include <math.h>
#include <stdint.h>

// ---------------- problem constants ----------------
#define B_  64
#define N_  256
#define D_  512
#define E_  10
#define M_  (B_*N_)        // 16384
#define KX_ (E_*D_)        // 5120  (edge part of stage-B K)
#define KB2_ (KX_+3*D_)    // 6656  (edge-hi + self: nhi*Whi, nlo*Whi, nhi*Wlo)
#define KI_B (KB2_/32)     // 208 k-iters (stage B)
#define KI_A 8             // k-iters (stage A, K=256, hi-only)

typedef __half fp16;

// ---------------- device scratch (static; no runtime allocation) ----------
__device__ unsigned g_bits[(size_t)E_*B_*N_*8];      // binary graphs bitmask
__device__ float    g_invneigh[M_];
__device__ float    g_w[M_];
__device__ float    g_nodeA[(size_t)M_*D_];          // fp32 node ping buffer
__device__ fp16     g_Bstack[(size_t)D_*KB2_];       // [d][kk] stacked weights
__device__ fp16     g_Zt[(size_t)B_*D_*N_];          // [b][d][j] = fp16(w_j * node[b,j,d])
__device__ fp16     g_Xhi[(size_t)M_*KX_];
__device__ fp16     g_nhi[(size_t)M_*D_],  g_nlo[(size_t)M_*D_];
__device__ fp16     g_nhi2[(size_t)M_*D_], g_nlo2[(size_t)M_*D_];

// ---------------- PTX helpers ----------------------------------------------
__device__ __forceinline__ uint32_t smem_u32(const void* p){
    uint32_t a; asm("{ .reg .u64 t; cvta.to.shared.u64 t, %1; cvt.u32.u64 %0, t; }"
                    : "=r"(a) : "l"(p)); return a;
}
__device__ __forceinline__ void cpa16(uint32_t dst, const void* src){
    asm volatile("cp.async.cg.shared.global [%0], [%1], 16;" :: "r"(dst), "l"(src));
}
#define CP_COMMIT() asm volatile("cp.async.commit_group;" ::: "memory")
#define CP_WAIT2()  asm volatile("cp.async.wait_group 2;" ::: "memory")

__device__ __forceinline__ void ldsm_x4(uint32_t* r, uint32_t addr){
    asm volatile("ldmatrix.sync.aligned.m8n8.x4.shared.b16 {%0,%1,%2,%3}, [%4];"
        : "=r"(r[0]),"=r"(r[1]),"=r"(r[2]),"=r"(r[3]) : "r"(addr));
}
__device__ __forceinline__ void mma16816(float* c, const uint32_t* a, const uint32_t* b){
    asm volatile("mma.sync.aligned.m16n8k16.row.col.f32.f16.f16.f32 "
        "{%0,%1,%2,%3},{%4,%5,%6,%7},{%8,%9},{%0,%1,%2,%3};"
        : "+f"(c[0]),"+f"(c[1]),"+f"(c[2]),"+f"(c[3])
        : "r"(a[0]),"r"(a[1]),"r"(a[2]),"r"(a[3]), "r"(b[0]),"r"(b[1]));
}

// smem: 4 stages; per stage As[128][40] + Bs[256][40] fp16 (80B pitch ->
// 8 consecutive rows hit distinct bank groups, conflict-free ldmatrix)
#define STG_BYTES 30720
#define OFF_B     10240
#define SMEM_DYN  (4*STG_BYTES)

// warp tile 64x64 (8 warps: 2 m x 4 n over 128x256 CTA tile)
__device__ __forceinline__ void warp_compute(uint32_t sA, uint32_t sB,
                                             int m_off, int n_off,
                                             float c[4][8][4], int lane){
    #pragma unroll
    for (int kh = 0; kh < 2; ++kh){
        int k16 = kh*16;
        uint32_t a[4][4];
        #pragma unroll
        for (int mt = 0; mt < 4; ++mt){
            int row = m_off + mt*16 + (lane & 15);
            ldsm_x4(a[mt], sA + (uint32_t)(row*40 + k16 + ((lane>>4)<<3))*2);
        }
        uint32_t bfr[4][4];
        #pragma unroll
        for (int np = 0; np < 4; ++np){
            int row = n_off + np*16 + (lane & 7) + ((lane>>4)&1)*8;
            ldsm_x4(bfr[np], sB + (uint32_t)(row*40 + k16 + (((lane>>3)&1)<<3))*2);
        }
        #pragma unroll
        for (int mt = 0; mt < 4; ++mt)
            #pragma unroll
            for (int nt = 0; nt < 8; ++nt)
                mma16816(c[mt][nt], a[mt], &bfr[nt>>1][(nt&1)*2]);
    }
}

// ---------------- preprocessing kernels ------------------------------------
__global__ void k_bits(const int* __restrict__ adj, const int* __restrict__ mask){
    int warp = threadIdx.x >> 5, lane = threadIdx.x & 31;
    int r = blockIdx.x * 8 + warp;
    int b = (r / N_) % B_;
    int i = r % N_;
    int mi = mask[b*N_ + i];
    const int* arow = adj + (size_t)r * N_;
    unsigned keep = 0;
    #pragma unroll
    for (int c = 0; c < 8; c++){
        int j = c*32 + lane;
        int bit = mi && mask[b*N_ + j] && arow[j] && (j != i);
        unsigned wrd = __ballot_sync(0xffffffffu, bit != 0);
        if (lane == c) keep = wrd;
    }
    if (lane < 8) g_bits[(size_t)r*8 + lane] = keep;
}
__global__ void k_neigh(){
    int t = blockIdx.x*blockDim.x + threadIdx.x;
    int b = t / N_;
    int s = 0;
    for (int e = 0; e < E_; e++){
        const unsigned* row = g_bits + (size_t)((e*B_+b)*N_ + (t % N_))*8;
        #pragma unroll
        for (int c = 0; c < 8; c++) s += __popc(row[c]);
    }
    float n = (float)s; if (n < 1.f) n = 1.f;
    g_invneigh[t] = 1.f / n;
}
// stacked weights: [0,5120): Wedge hi; [5120,5632): Wself hi (pairs nhi);
// [5632,6144): Wself hi (pairs nlo); [6144,6656): Wself lo (pairs nhi)
__global__ void k_bstack(const float* __restrict__ We, const float* __restrict__ Ws){
    int idx = blockIdx.x*256 + threadIdx.x;
    if (idx >= D_*KB2_) return;
    int d = idx / KB2_, kk = idx % KB2_;
    fp16 v;
    if (kk < KX_){
        int e = kk / D_, k2 = kk % D_;
        v = __float2half(We[((size_t)e*D_ + d)*D_ + k2]);
    } else {
        int off = kk - KX_;
        int seg = off >> 9;            // 0,1,2
        int k2  = off & 511;
        float w = Ws[(size_t)d*D_ + k2];
        fp16 h = __float2half(w);
        v = (seg < 2) ? h : __float2half(w - __half2float(h));
    }
    g_Bstack[(size_t)d*KB2_ + kk] = v;
}

// ---------------- per-iteration elementwise kernels -------------------------
__global__ void k_w(const float* __restrict__ node0, int useScratch,
                    const float* __restrict__ Wnw, const float* __restrict__ bnw,
                    float* __restrict__ woutBase, int it){
    int warp = threadIdx.x >> 5, lane = threadIdx.x & 31;
    int r = blockIdx.x*8 + warp;
    const float* node = useScratch ? g_nodeA : node0;
    const float4* nr = (const float4*)(node + (size_t)r*D_);
    const float4* wr = (const float4*)Wnw;
    float s = 0.f;
    #pragma unroll
    for (int c = 0; c < 4; c++){
        float4 a = nr[c*32 + lane], w = wr[c*32 + lane];
        s += a.x*w.x + a.y*w.y + a.z*w.z + a.w*w.w;
    }
    #pragma unroll
    for (int o = 16; o; o >>= 1) s += __shfl_down_sync(0xffffffffu, s, o);
    if (lane == 0){
        float z = s + bnw[0];
        float w = 1.f / (1.f + expf(-z));
        g_w[r] = w;
        int b = r / N_, n = r % N_;
        woutBase[(size_t)b*(2*N_) + it*N_ + n] = w;
    }
}
// transpose w*node -> Zt (fp16 hi only); iter 0 also emits nhi/nlo
__global__ void k_zt(const float* __restrict__ node0, int useScratch){
    __shared__ float s[32][33];
    const float* node = useScratch ? g_nodeA : node0;
    int b = blockIdx.z, d0 = blockIdx.x*32, j0 = blockIdx.y*32;
    int tx = threadIdx.x, ty = threadIdx.y;
    int j = j0 + ty;
    size_t gidx = ((size_t)b*N_ + j)*D_ + d0 + tx;
    float raw = node[gidx];
    if (!useScratch){
        fp16 h = __float2half(raw);
        g_nhi[gidx] = h;
        g_nlo[gidx] = __float2half(raw - __half2float(h));
    }
    s[ty][tx] = raw * g_w[b*N_ + j];
    __syncthreads();
    g_Zt[((size_t)b*D_ + d0 + ty)*N_ + j0 + tx] = __float2half(s[tx][ty]);
}

// ---------------- stage A GEMM: Xhi = fp16((G @ Zt) * inv_neigh) ------------
// CTA tile 128x256; A(=G fp16 0/1) expanded from g_bits in-kernel; K=256.
__global__ void __launch_bounds__(256, 1) k_gemmA(){
    extern __shared__ char dsm[];
    uint32_t sbase = smem_u32(dsm);
    int tid = threadIdx.x, wid = tid >> 5, lane = tid & 31;
    int dBase = blockIdx.x * 256;           // 0 or 256
    int y = blockIdx.y;                     // be*2 + mhalf
    int mhalf = y & 1; int be = y >> 1;
    int e = be % E_, b = be / E_;
    int m_off = (wid >> 2) * 64;
    int n_off = (wid & 3) * 64;

    const fp16* Zbase = g_Zt + ((size_t)b*D_ + dBase) * (size_t)N_;
    const unsigned* bitbase = g_bits + (size_t)(((size_t)e*B_ + b)*N_ + mhalf*128)*8;

    int rA = tid >> 1, hsel = tid & 1;      // A expand: row, 16-bit half

    auto loadB = [&](int itk, int s){
        uint32_t sB = sbase + s*STG_BYTES + OFF_B;
        const fp16* src = Zbase + (size_t)tid*N_ + itk*32;
        uint32_t d0 = sB + (uint32_t)(tid*40)*2;
        cpa16(d0,      src);
        cpa16(d0 + 16, src + 8);
        cpa16(d0 + 32, src + 16);
        cpa16(d0 + 48, src + 24);
        CP_COMMIT();
    };
    auto expandA = [&](int itk, int s){
        unsigned w32 = bitbase[(size_t)rA*8 + (itk & 7)];
        unsigned bits = (w32 >> (hsel*16)) & 0xFFFFu;
        uint32_t u[8];
        #pragma unroll
        for (int q = 0; q < 8; ++q){
            u[q] = ((bits >> (2*q)) & 1u ? 0x3C00u : 0u)
                 | ((bits >> (2*q+1)) & 1u ? 0x3C000000u : 0u);
        }
        char* dst = dsm + s*STG_BYTES + (rA*40 + hsel*16)*2;
        *(uint4*)(dst)      = make_uint4(u[0],u[1],u[2],u[3]);
        *(uint4*)(dst + 16) = make_uint4(u[4],u[5],u[6],u[7]);
    };

    float c[4][8][4];
    #pragma unroll
    for (int i = 0; i < 4; ++i)
        #pragma unroll
        for (int j = 0; j < 8; ++j)
            #pragma unroll
            for (int q = 0; q < 4; ++q) c[i][j][q] = 0.f;

    expandA(0, 0);
    loadB(0, 0); loadB(1, 1); loadB(2, 2);
    for (int it = 0; it < KI_A; ++it){
        CP_WAIT2();
        __syncthreads();
        if (it + 1 < KI_A) expandA(it + 1, (it + 1) & 3);
        if (it + 3 < KI_A) loadB(it + 3, (it + 3) & 3); else CP_COMMIT();
        int s = it & 3;
        warp_compute(sbase + s*STG_BYTES, sbase + s*STG_BYTES + OFF_B,
                     m_off, n_off, c, lane);
    }

    // epilogue: * inv_neigh, fp16 store
    #pragma unroll
    for (int mt = 0; mt < 4; ++mt){
        int i1 = mhalf*128 + m_off + mt*16 + (lane >> 2);
        int r1 = b*N_ + i1;
        float inv1 = g_invneigh[r1];
        float inv2 = g_invneigh[r1 + 8];
        #pragma unroll
        for (int nt = 0; nt < 8; ++nt){
            int col = e*D_ + dBase + n_off + nt*8 + (lane & 3)*2;
            fp16 h0 = __float2half(c[mt][nt][0]*inv1);
            fp16 h1 = __float2half(c[mt][nt][1]*inv1);
            fp16 h2 = __float2half(c[mt][nt][2]*inv2);
            fp16 h3 = __float2half(c[mt][nt][3]*inv2);
            *(uint32_t*)(g_Xhi + (size_t)r1*KX_ + col) =
                (uint32_t)__half_as_ushort(h0) | ((uint32_t)__half_as_ushort(h1) << 16);
            *(uint32_t*)(g_Xhi + (size_t)(r1+8)*KX_ + col) =
                (uint32_t)__half_as_ushort(h2) | ((uint32_t)__half_as_ushort(h3) << 16);
        }
    }
}

// ---------------- stage B GEMM: out = relu([Xhi|nhi|nlo|nhi] @ Bstack + b) --
// CTA tile 128x256, K=6656.
__global__ void __launch_bounds__(256, 1) k_gemmB(const float* __restrict__ bself,
                                                  float* __restrict__ out0,
                                                  int srcSel, int outMode){
    extern __shared__ char dsm[];
    uint32_t sbase = smem_u32(dsm);
    int tid = threadIdx.x, wid = tid >> 5, lane = tid & 31;
    int dBase = blockIdx.x * 256;
    int mBase = blockIdx.y * 128;
    int m_off = (wid >> 2) * 64;
    int n_off = (wid & 3) * 64;

    const fp16* NHI = srcSel ? g_nhi2 : g_nhi;
    const fp16* NLO = srcSel ? g_nlo2 : g_nlo;
    int rA = tid >> 1, cA = (tid & 1)*2;

    auto load = [&](int itk, int s){
        uint32_t sA = sbase + s*STG_BYTES;
        uint32_t sB = sA + OFF_B;
        int rr = itk * 32;
        const fp16* Ab; size_t ap;
        if (rr < KX_){ Ab = g_Xhi + (size_t)mBase*KX_ + rr; ap = KX_; }
        else {
            int off = rr - KX_;
            const fp16* src = (off < 512) ? NHI : (off < 1024 ? NLO : NHI);
            int k2 = off & 511;
            Ab = src + (size_t)mBase*D_ + k2; ap = D_;
        }
        uint32_t dA = sA + (uint32_t)(rA*40 + cA*8)*2;
        cpa16(dA,      Ab + (size_t)rA*ap + cA*8);
        cpa16(dA + 16, Ab + (size_t)rA*ap + cA*8 + 8);
        const fp16* Bb = g_Bstack + (size_t)(dBase + tid)*KB2_ + rr;
        uint32_t dB = sB + (uint32_t)(tid*40)*2;
        cpa16(dB,      Bb);
        cpa16(dB + 16, Bb + 8);
        cpa16(dB + 32, Bb + 16);
        cpa16(dB + 48, Bb + 24);
        CP_COMMIT();
    };

    float c[4][8][4];
    #pragma unroll
    for (int i = 0; i < 4; ++i)
        #pragma unroll
        for (int j = 0; j < 8; ++j)
            #pragma unroll
            for (int q = 0; q < 4; ++q) c[i][j][q] = 0.f;

    load(0, 0); load(1, 1); load(2, 2);
    for (int it = 0; it < KI_B; ++it){
        CP_WAIT2();
        __syncthreads();
        if (it + 3 < KI_B) load(it + 3, (it + 3) & 3); else CP_COMMIT();
        int s = it & 3;
        warp_compute(sbase + s*STG_BYTES, sbase + s*STG_BYTES + OFF_B,
                     m_off, n_off, c, lane);
    }

    #pragma unroll
    for (int mt = 0; mt < 4; ++mt){
        int m1 = mBase + m_off + mt*16 + (lane >> 2);
        #pragma unroll
        for (int nt = 0; nt < 8; ++nt){
            int n = dBase + n_off + nt*8 + (lane & 3)*2;
            float bi0 = __ldg(bself + n), bi1 = __ldg(bself + n + 1);
            float v0 = c[mt][nt][0] + bi0, v1 = c[mt][nt][1] + bi1;
            float v2 = c[mt][nt][2] + bi0, v3 = c[mt][nt][3] + bi1;
            v0 = v0 > 0.f ? v0 : 0.f; v1 = v1 > 0.f ? v1 : 0.f;
            v2 = v2 > 0.f ? v2 : 0.f; v3 = v3 > 0.f ? v3 : 0.f;
            if (outMode){
                // intermediate: write fp32 scratch + fp16 hi/lo for next iter
                *(float2*)(g_nodeA + (size_t)m1*D_ + n)     = make_float2(v0, v1);
                *(float2*)(g_nodeA + (size_t)(m1+8)*D_ + n) = make_float2(v2, v3);
                fp16 h0=__float2half(v0), h1=__float2half(v1);
                fp16 h2=__float2half(v2), h3=__float2half(v3);
                fp16 l0=__float2half(v0-__half2float(h0));
                fp16 l1=__float2half(v1-__half2float(h1));
                fp16 l2=__float2half(v2-__half2float(h2));
                fp16 l3=__float2half(v3-__half2float(h3));
                *(uint32_t*)(g_nhi2 + (size_t)m1*D_ + n)     = (uint32_t)__half_as_ushort(h0)|((uint32_t)__half_as_ushort(h1)<<16);
                *(uint32_t*)(g_nhi2 + (size_t)(m1+8)*D_ + n) = (uint32_t)__half_as_ushort(h2)|((uint32_t)__half_as_ushort(h3)<<16);
                *(uint32_t*)(g_nlo2 + (size_t)m1*D_ + n)     = (uint32_t)__half_as_ushort(l0)|((uint32_t)__half_as_ushort(l1)<<16);
                *(uint32_t*)(g_nlo2 + (size_t)(m1+8)*D_ + n) = (uint32_t)__half_as_ushort(l2)|((uint32_t)__half_as_ushort(l3)<<16);
            } else {
                *(float2*)(out0 + (size_t)m1*D_ + n)     = make_float2(v0, v1);
                *(float2*)(out0 + (size_t)(m1+8)*D_ + n) = make_float2(v2, v3);
            }
        }
    }
}

// ---------------- launch ----------------------------------------------------
extern "C" void kernel_launch(void* const* d_in, const int* in_sizes, int n_in,
                              void* d_out, int out_size){
    const float* node  = (const float*)d_in[0];
    const float* Wnw   = (const float*)d_in[1];
    const float* bnw   = (const float*)d_in[2];
    const float* Wself = (const float*)d_in[3];
    const float* bself = (const float*)d_in[4];
    const float* Wedge = (const float*)d_in[5];
    const int*   mask  = (const int*)d_in[6];
    const int*   adj   = (const int*)d_in[7];

    float* out  = (float*)d_out;
    float* outW = out + (size_t)M_*D_;

    cudaFuncSetAttribute(k_gemmA, cudaFuncAttributeMaxDynamicSharedMemorySize, SMEM_DYN);
    cudaFuncSetAttribute(k_gemmB, cudaFuncAttributeMaxDynamicSharedMemorySize, SMEM_DYN);

    // iteration-invariant preprocessing
    k_bstack<<<(D_*KB2_ + 255)/256, 256>>>(Wedge, Wself);
    k_bits  <<<(E_*B_*N_)/8, 256>>>(adj, mask);
    k_neigh <<<M_/256, 256>>>();

    // ---- iteration 0: node -> g_nodeA (+ nhi2/nlo2) ----
    k_w    <<<M_/8, 256>>>(node, 0, Wnw, bnw, outW, 0);
    k_zt   <<<dim3(16, 8, B_), dim3(32, 32)>>>(node, 0);
    k_gemmA<<<dim3(2, B_*E_*2), 256, SMEM_DYN>>>();
    k_gemmB<<<dim3(2, M_/128), 256, SMEM_DYN>>>(bself, out, 0, 1);

    // ---- iteration 1: g_nodeA -> d_out ----
    k_w    <<<M_/8, 256>>>(node, 1, Wnw, bnw, outW, 1);
    k_zt   <<<dim3(16, 8, B_), dim3(32, 32)>>>(node, 1);
    k_gemmA<<<dim3(2, B_*E_*2), 256, SMEM_DYN>>>();
    k_gemmB<<<dim3(2, M_/128), 256, SMEM_DYN>>>(bself, out, 1, 0);
}

// round 7
// speedup vs baseline: 3.9455x; 1.1230x over previous
#include <cuda_runtime.h>
#include <cuda_fp16.h>
#include <math.h>
#include <stdint.h>

// ---------------- problem constants ----------------
#define B_  64
#define N_  256
#define D_  512
#define E_  10
#define M_  (B_*N_)        // 16384
#define KX_ (E_*D_)        // 5120  (edge part of stage-B K)
#define KB_ (KX_+D_)       // 5632  (edge-hi + self-hi)
#define KI_B (KB_/32)      // 176 k-iters (stage B)
#define KI_A 8             // k-iters (stage A, K=256, hi-only)

typedef __half fp16;

// ---------------- device scratch (static; no runtime allocation) ----------
__device__ unsigned g_bits[(size_t)E_*B_*N_*8];      // binary graphs bitmask
__device__ float    g_invneigh[M_];
__device__ float    g_w[M_];
__device__ float    g_nodeA[(size_t)M_*D_];          // fp32 node ping buffer
__device__ fp16     g_Bstack[(size_t)D_*KB_];        // [d][kk]: Wedge_hi | Wself_hi
__device__ fp16     g_Zt[(size_t)B_*D_*N_];          // [b][d][j] = fp16(w_j*node[b,j,d])
__device__ fp16     g_Xhi[(size_t)M_*KX_];
__device__ fp16     g_nhi[(size_t)M_*D_], g_nhi2[(size_t)M_*D_];

// ---------------- PTX helpers ----------------------------------------------
__device__ __forceinline__ uint32_t smem_u32(const void* p){
    uint32_t a; asm("{ .reg .u64 t; cvta.to.shared.u64 t, %1; cvt.u32.u64 %0, t; }"
                    : "=r"(a) : "l"(p)); return a;
}
__device__ __forceinline__ void cpa16(uint32_t dst, const void* src){
    asm volatile("cp.async.cg.shared.global [%0], [%1], 16;" :: "r"(dst), "l"(src));
}
#define CP_COMMIT() asm volatile("cp.async.commit_group;" ::: "memory")
#define CP_WAIT2()  asm volatile("cp.async.wait_group 2;" ::: "memory")

__device__ __forceinline__ void ldsm_x4(uint32_t* r, uint32_t addr){
    asm volatile("ldmatrix.sync.aligned.m8n8.x4.shared.b16 {%0,%1,%2,%3}, [%4];"
        : "=r"(r[0]),"=r"(r[1]),"=r"(r[2]),"=r"(r[3]) : "r"(addr));
}
__device__ __forceinline__ void mma16816(float* c, const uint32_t* a, const uint32_t* b){
    asm volatile("mma.sync.aligned.m16n8k16.row.col.f32.f16.f16.f32 "
        "{%0,%1,%2,%3},{%4,%5,%6,%7},{%8,%9},{%0,%1,%2,%3};"
        : "+f"(c[0]),"+f"(c[1]),"+f"(c[2]),"+f"(c[3])
        : "r"(a[0]),"r"(a[1]),"r"(a[2]),"r"(a[3]), "r"(b[0]),"r"(b[1]));
}

// smem: 4 stages; per stage As[128][40] + Bs[256][40] fp16 (80B pitch ->
// 8 consecutive rows hit distinct bank groups, conflict-free ldmatrix)
#define STG_BYTES 30720
#define OFF_B     10240
#define SMEM_DYN  (4*STG_BYTES)

// warp tile 64x64 (8 warps: 2 m x 4 n over 128x256 CTA tile)
__device__ __forceinline__ void warp_compute(uint32_t sA, uint32_t sB,
                                             int m_off, int n_off,
                                             float c[4][8][4], int lane){
    #pragma unroll
    for (int kh = 0; kh < 2; ++kh){
        int k16 = kh*16;
        uint32_t a[4][4];
        #pragma unroll
        for (int mt = 0; mt < 4; ++mt){
            int row = m_off + mt*16 + (lane & 15);
            ldsm_x4(a[mt], sA + (uint32_t)(row*40 + k16 + ((lane>>4)<<3))*2);
        }
        uint32_t bfr[4][4];
        #pragma unroll
        for (int np = 0; np < 4; ++np){
            int row = n_off + np*16 + (lane & 7) + ((lane>>4)&1)*8;
            ldsm_x4(bfr[np], sB + (uint32_t)(row*40 + k16 + (((lane>>3)&1)<<3))*2);
        }
        #pragma unroll
        for (int mt = 0; mt < 4; ++mt)
            #pragma unroll
            for (int nt = 0; nt < 8; ++nt)
                mma16816(c[mt][nt], a[mt], &bfr[nt>>1][(nt&1)*2]);
    }
}

// ---------------- preprocessing kernels ------------------------------------
__global__ void k_bits(const int* __restrict__ adj, const int* __restrict__ mask){
    int warp = threadIdx.x >> 5, lane = threadIdx.x & 31;
    int r = blockIdx.x * 8 + warp;
    int b = (r / N_) % B_;
    int i = r % N_;
    int mi = mask[b*N_ + i];
    const int* arow = adj + (size_t)r * N_;
    unsigned keep = 0;
    #pragma unroll
    for (int c = 0; c < 8; c++){
        int j = c*32 + lane;
        int bit = mi && mask[b*N_ + j] && arow[j] && (j != i);
        unsigned wrd = __ballot_sync(0xffffffffu, bit != 0);
        if (lane == c) keep = wrd;
    }
    if (lane < 8) g_bits[(size_t)r*8 + lane] = keep;
}
__global__ void k_neigh(){
    int t = blockIdx.x*blockDim.x + threadIdx.x;
    int b = t / N_;
    int s = 0;
    for (int e = 0; e < E_; e++){
        const unsigned* row = g_bits + (size_t)((e*B_+b)*N_ + (t % N_))*8;
        #pragma unroll
        for (int c = 0; c < 8; c++) s += __popc(row[c]);
    }
    float n = (float)s; if (n < 1.f) n = 1.f;
    g_invneigh[t] = 1.f / n;
}
// stacked weights: [0,5120): Wedge hi; [5120,5632): Wself hi
__global__ void k_bstack(const float* __restrict__ We, const float* __restrict__ Ws){
    int idx = blockIdx.x*256 + threadIdx.x;
    if (idx >= D_*KB_) return;
    int d = idx / KB_, kk = idx % KB_;
    float w;
    if (kk < KX_){
        int e = kk / D_, k2 = kk % D_;
        w = We[((size_t)e*D_ + d)*D_ + k2];
    } else {
        w = Ws[(size_t)d*D_ + (kk - KX_)];
    }
    g_Bstack[(size_t)d*KB_ + kk] = __float2half(w);
}

// ---------------- per-iteration elementwise kernels -------------------------
__global__ void k_w(const float* __restrict__ node0, int useScratch,
                    const float* __restrict__ Wnw, const float* __restrict__ bnw,
                    float* __restrict__ woutBase, int it){
    int warp = threadIdx.x >> 5, lane = threadIdx.x & 31;
    int r = blockIdx.x*8 + warp;
    const float* node = useScratch ? g_nodeA : node0;
    const float4* nr = (const float4*)(node + (size_t)r*D_);
    const float4* wr = (const float4*)Wnw;
    float s = 0.f;
    #pragma unroll
    for (int c = 0; c < 4; c++){
        float4 a = nr[c*32 + lane], w = wr[c*32 + lane];
        s += a.x*w.x + a.y*w.y + a.z*w.z + a.w*w.w;
    }
    #pragma unroll
    for (int o = 16; o; o >>= 1) s += __shfl_down_sync(0xffffffffu, s, o);
    if (lane == 0){
        float z = s + bnw[0];
        float w = 1.f / (1.f + expf(-z));
        g_w[r] = w;
        int b = r / N_, n = r % N_;
        woutBase[(size_t)b*(2*N_) + it*N_ + n] = w;
    }
}
// transpose w*node -> Zt (fp16); iter 0 also emits nhi
__global__ void k_zt(const float* __restrict__ node0, int useScratch){
    __shared__ float s[32][33];
    const float* node = useScratch ? g_nodeA : node0;
    int b = blockIdx.z, d0 = blockIdx.x*32, j0 = blockIdx.y*32;
    int tx = threadIdx.x, ty = threadIdx.y;
    int j = j0 + ty;
    size_t gidx = ((size_t)b*N_ + j)*D_ + d0 + tx;
    float raw = node[gidx];
    if (!useScratch) g_nhi[gidx] = __float2half(raw);
    s[ty][tx] = raw * g_w[b*N_ + j];
    __syncthreads();
    g_Zt[((size_t)b*D_ + d0 + ty)*N_ + j0 + tx] = __float2half(s[tx][ty]);
}

// ---------------- stage A GEMM: Xhi = fp16((G @ Zt) * inv_neigh) ------------
// CTA tile 128x256; A(=G fp16 0/1) expanded from g_bits in-kernel; K=256.
__global__ void __launch_bounds__(256, 1) k_gemmA(){
    extern __shared__ char dsm[];
    uint32_t sbase = smem_u32(dsm);
    int tid = threadIdx.x, wid = tid >> 5, lane = tid & 31;
    int dBase = blockIdx.x * 256;           // 0 or 256
    int y = blockIdx.y;                     // be*2 + mhalf
    int mhalf = y & 1; int be = y >> 1;
    int e = be % E_, b = be / E_;
    int m_off = (wid >> 2) * 64;
    int n_off = (wid & 3) * 64;

    const fp16* Zbase = g_Zt + ((size_t)b*D_ + dBase) * (size_t)N_;
    const unsigned* bitbase = g_bits + (size_t)(((size_t)e*B_ + b)*N_ + mhalf*128)*8;

    int rA = tid >> 1, hsel = tid & 1;      // A expand: row, 16-bit half

    auto loadB = [&](int itk, int s){
        uint32_t sB = sbase + s*STG_BYTES + OFF_B;
        const fp16* src = Zbase + (size_t)tid*N_ + itk*32;
        uint32_t d0 = sB + (uint32_t)(tid*40)*2;
        cpa16(d0,      src);
        cpa16(d0 + 16, src + 8);
        cpa16(d0 + 32, src + 16);
        cpa16(d0 + 48, src + 24);
        CP_COMMIT();
    };
    auto expandA = [&](int itk, int s){
        unsigned w32 = bitbase[(size_t)rA*8 + (itk & 7)];
        unsigned bits = (w32 >> (hsel*16)) & 0xFFFFu;
        uint32_t u[8];
        #pragma unroll
        for (int q = 0; q < 8; ++q){
            u[q] = ((bits >> (2*q)) & 1u ? 0x3C00u : 0u)
                 | ((bits >> (2*q+1)) & 1u ? 0x3C000000u : 0u);
        }
        char* dst = dsm + s*STG_BYTES + (rA*40 + hsel*16)*2;
        *(uint4*)(dst)      = make_uint4(u[0],u[1],u[2],u[3]);
        *(uint4*)(dst + 16) = make_uint4(u[4],u[5],u[6],u[7]);
    };

    float c[4][8][4];
    #pragma unroll
    for (int i = 0; i < 4; ++i)
        #pragma unroll
        for (int j = 0; j < 8; ++j)
            #pragma unroll
            for (int q = 0; q < 4; ++q) c[i][j][q] = 0.f;

    expandA(0, 0);
    loadB(0, 0); loadB(1, 1); loadB(2, 2);
    for (int it = 0; it < KI_A; ++it){
        CP_WAIT2();
        __syncthreads();
        if (it + 1 < KI_A) expandA(it + 1, (it + 1) & 3);
        if (it + 3 < KI_A) loadB(it + 3, (it + 3) & 3); else CP_COMMIT();
        int s = it & 3;
        warp_compute(sbase + s*STG_BYTES, sbase + s*STG_BYTES + OFF_B,
                     m_off, n_off, c, lane);
    }

    // epilogue: * inv_neigh, fp16 store
    #pragma unroll
    for (int mt = 0; mt < 4; ++mt){
        int i1 = mhalf*128 + m_off + mt*16 + (lane >> 2);
        int r1 = b*N_ + i1;
        float inv1 = g_invneigh[r1];
        float inv2 = g_invneigh[r1 + 8];
        #pragma unroll
        for (int nt = 0; nt < 8; ++nt){
            int col = e*D_ + dBase + n_off + nt*8 + (lane & 3)*2;
            fp16 h0 = __float2half(c[mt][nt][0]*inv1);
            fp16 h1 = __float2half(c[mt][nt][1]*inv1);
            fp16 h2 = __float2half(c[mt][nt][2]*inv2);
            fp16 h3 = __float2half(c[mt][nt][3]*inv2);
            *(uint32_t*)(g_Xhi + (size_t)r1*KX_ + col) =
                (uint32_t)__half_as_ushort(h0) | ((uint32_t)__half_as_ushort(h1) << 16);
            *(uint32_t*)(g_Xhi + (size_t)(r1+8)*KX_ + col) =
                (uint32_t)__half_as_ushort(h2) | ((uint32_t)__half_as_ushort(h3) << 16);
        }
    }
}

// ---------------- stage B GEMM: out = relu([Xhi|nhi] @ Bstack + b) ----------
// CTA tile 128x256, K=5632.
__global__ void __launch_bounds__(256, 1) k_gemmB(const float* __restrict__ bself,
                                                  float* __restrict__ out0,
                                                  int srcSel, int outMode){
    extern __shared__ char dsm[];
    uint32_t sbase = smem_u32(dsm);
    int tid = threadIdx.x, wid = tid >> 5, lane = tid & 31;
    int dBase = blockIdx.x * 256;
    int mBase = blockIdx.y * 128;
    int m_off = (wid >> 2) * 64;
    int n_off = (wid & 3) * 64;

    const fp16* NHI = srcSel ? g_nhi2 : g_nhi;
    int rA = tid >> 1, cA = (tid & 1)*2;

    auto load = [&](int itk, int s){
        uint32_t sA = sbase + s*STG_BYTES;
        uint32_t sB = sA + OFF_B;
        int rr = itk * 32;
        const fp16* Ab; size_t ap;
        if (rr < KX_){ Ab = g_Xhi + (size_t)mBase*KX_ + rr; ap = KX_; }
        else         { Ab = NHI + (size_t)mBase*D_ + (rr - KX_); ap = D_; }
        uint32_t dA = sA + (uint32_t)(rA*40 + cA*8)*2;
        cpa16(dA,      Ab + (size_t)rA*ap + cA*8);
        cpa16(dA + 16, Ab + (size_t)rA*ap + cA*8 + 8);
        const fp16* Bb = g_Bstack + (size_t)(dBase + tid)*KB_ + rr;
        uint32_t dB = sB + (uint32_t)(tid*40)*2;
        cpa16(dB,      Bb);
        cpa16(dB + 16, Bb + 8);
        cpa16(dB + 32, Bb + 16);
        cpa16(dB + 48, Bb + 24);
        CP_COMMIT();
    };

    float c[4][8][4];
    #pragma unroll
    for (int i = 0; i < 4; ++i)
        #pragma unroll
        for (int j = 0; j < 8; ++j)
            #pragma unroll
            for (int q = 0; q < 4; ++q) c[i][j][q] = 0.f;

    load(0, 0); load(1, 1); load(2, 2);
    for (int it = 0; it < KI_B; ++it){
        CP_WAIT2();
        __syncthreads();
        if (it + 3 < KI_B) load(it + 3, (it + 3) & 3); else CP_COMMIT();
        int s = it & 3;
        warp_compute(sbase + s*STG_BYTES, sbase + s*STG_BYTES + OFF_B,
                     m_off, n_off, c, lane);
    }

    #pragma unroll
    for (int mt = 0; mt < 4; ++mt){
        int m1 = mBase + m_off + mt*16 + (lane >> 2);
        #pragma unroll
        for (int nt = 0; nt < 8; ++nt){
            int n = dBase + n_off + nt*8 + (lane & 3)*2;
            float bi0 = __ldg(bself + n), bi1 = __ldg(bself + n + 1);
            float v0 = c[mt][nt][0] + bi0, v1 = c[mt][nt][1] + bi1;
            float v2 = c[mt][nt][2] + bi0, v3 = c[mt][nt][3] + bi1;
            v0 = v0 > 0.f ? v0 : 0.f; v1 = v1 > 0.f ? v1 : 0.f;
            v2 = v2 > 0.f ? v2 : 0.f; v3 = v3 > 0.f ? v3 : 0.f;
            if (outMode){
                // intermediate: write fp32 scratch + fp16 hi for next iter
                *(float2*)(g_nodeA + (size_t)m1*D_ + n)     = make_float2(v0, v1);
                *(float2*)(g_nodeA + (size_t)(m1+8)*D_ + n) = make_float2(v2, v3);
                fp16 h0=__float2half(v0), h1=__float2half(v1);
                fp16 h2=__float2half(v2), h3=__float2half(v3);
                *(uint32_t*)(g_nhi2 + (size_t)m1*D_ + n)     = (uint32_t)__half_as_ushort(h0)|((uint32_t)__half_as_ushort(h1)<<16);
                *(uint32_t*)(g_nhi2 + (size_t)(m1+8)*D_ + n) = (uint32_t)__half_as_ushort(h2)|((uint32_t)__half_as_ushort(h3)<<16);
            } else {
                *(float2*)(out0 + (size_t)m1*D_ + n)     = make_float2(v0, v1);
                *(float2*)(out0 + (size_t)(m1+8)*D_ + n) = make_float2(v2, v3);
            }
        }
    }
}

// ---------------- launch ----------------------------------------------------
extern "C" void kernel_launch(void* const* d_in, const int* in_sizes, int n_in,
                              void* d_out, int out_size){
    const float* node  = (const float*)d_in[0];
    const float* Wnw   = (const float*)d_in[1];
    const float* bnw   = (const float*)d_in[2];
    const float* Wself = (const float*)d_in[3];
    const float* bself = (const float*)d_in[4];
    const float* Wedge = (const float*)d_in[5];
    const int*   mask  = (const int*)d_in[6];
    const int*   adj   = (const int*)d_in[7];

    float* out  = (float*)d_out;
    float* outW = out + (size_t)M_*D_;

    cudaFuncSetAttribute(k_gemmA, cudaFuncAttributeMaxDynamicSharedMemorySize, SMEM_DYN);
    cudaFuncSetAttribute(k_gemmB, cudaFuncAttributeMaxDynamicSharedMemorySize, SMEM_DYN);

    // iteration-invariant preprocessing
    k_bstack<<<(D_*KB_ + 255)/256, 256>>>(Wedge, Wself);
    k_bits  <<<(E_*B_*N_)/8, 256>>>(adj, mask);
    k_neigh <<<M_/256, 256>>>();

    // ---- iteration 0: node -> g_nodeA (+ nhi2) ----
    k_w    <<<M_/8, 256>>>(node, 0, Wnw, bnw, outW, 0);
    k_zt   <<<dim3(16, 8, B_), dim3(32, 32)>>>(node, 0);
    k_gemmA<<<dim3(2, B_*E_*2), 256, SMEM_DYN>>>();
    k_gemmB<<<dim3(2, M_/128), 256, SMEM_DYN>>>(bself, out, 0, 1);

    // ---- iteration 1: g_nodeA -> d_out ----
    k_w    <<<M_/8, 256>>>(node, 1, Wnw, bnw, outW, 1);
    k_zt   <<<dim3(16, 8, B_), dim3(32, 32)>>>(node, 1);
    k_gemmA<<<dim3(2, B_*E_*2), 256, SMEM_DYN>>>();
    k_gemmB<<<dim3(2, M_/128), 256, SMEM_DYN>>>(bself, out, 1, 0);
}

// round 8
// speedup vs baseline: 5.9984x; 1.5203x over previous
#include <cuda_runtime.h>
#include <cuda_fp16.h>
#include <math.h>
#include <stdint.h>

// ---------------- problem constants ----------------
#define B_  64
#define N_  256
#define D_  512
#define E_  10
#define M_  (B_*N_)        // 16384
#define KX_ (E_*D_)        // 5120  (edge part of stage-B K)
#define KB_ (KX_+D_)       // 5632  (edge-hi + self-hi)
#define KI_B (KB_/32)      // 176 k-iters (stage B)
#define KSLF (KX_/32)      // 160 = k-iter where self segment starts
#define KI_A 8             // k-iters (stage A, K=256)

typedef __half fp16;

// ---------------- device scratch (static; no runtime allocation) ----------
__device__ unsigned g_bits[(size_t)E_*B_*N_*8];      // binary graphs bitmask
__device__ float    g_invneigh[M_];
__device__ float    g_w[M_];
__device__ float    g_nodeA[(size_t)M_*D_];          // fp32 node ping buffer
__device__ fp16     g_Bstack[(size_t)D_*KB_];        // [d][kk]: Wedge_hi | Wself_hi
__device__ fp16     g_Zt[(size_t)B_*D_*N_];          // [b][d][j] = fp16(w_j*node[b,j,d])
__device__ fp16     g_Xhi[(size_t)M_*KX_];           // packed-rank rows
__device__ fp16     g_nhi[(size_t)M_*D_], g_nhi2[(size_t)M_*D_];
// mask packing
__device__ int      g_gperm[M_];     // rank -> orig row (actives first, global)
__device__ int      g_cnt[B_];       // active count per batch
__device__ int      g_aoff[B_+1];    // prefix of g_cnt
__device__ int      g_acnt;          // total active rows

// ---------------- PTX helpers ----------------------------------------------
__device__ __forceinline__ uint32_t smem_u32(const void* p){
    uint32_t a; asm("{ .reg .u64 t; cvta.to.shared.u64 t, %1; cvt.u32.u64 %0, t; }"
                    : "=r"(a) : "l"(p)); return a;
}
__device__ __forceinline__ void cpa16(uint32_t dst, const void* src){
    asm volatile("cp.async.cg.shared.global [%0], [%1], 16;" :: "r"(dst), "l"(src));
}
#define CP_COMMIT() asm volatile("cp.async.commit_group;" ::: "memory")
#define CP_WAIT2()  asm volatile("cp.async.wait_group 2;" ::: "memory")

__device__ __forceinline__ void ldsm_x4(uint32_t* r, uint32_t addr){
    asm volatile("ldmatrix.sync.aligned.m8n8.x4.shared.b16 {%0,%1,%2,%3}, [%4];"
        : "=r"(r[0]),"=r"(r[1]),"=r"(r[2]),"=r"(r[3]) : "r"(addr));
}
__device__ __forceinline__ void mma16816(float* c, const uint32_t* a, const uint32_t* b){
    asm volatile("mma.sync.aligned.m16n8k16.row.col.f32.f16.f16.f32 "
        "{%0,%1,%2,%3},{%4,%5,%6,%7},{%8,%9},{%0,%1,%2,%3};"
        : "+f"(c[0]),"+f"(c[1]),"+f"(c[2]),"+f"(c[3])
        : "r"(a[0]),"r"(a[1]),"r"(a[2]),"r"(a[3]), "r"(b[0]),"r"(b[1]));
}

#define STG_BYTES 30720
#define OFF_B     10240
#define SMEM_DYN  (4*STG_BYTES)

// warp tile 64x64 (8 warps: 2 m x 4 n over 128x256 CTA tile)
__device__ __forceinline__ void warp_compute(uint32_t sA, uint32_t sB,
                                             int m_off, int n_off,
                                             float c[4][8][4], int lane){
    #pragma unroll
    for (int kh = 0; kh < 2; ++kh){
        int k16 = kh*16;
        uint32_t a[4][4];
        #pragma unroll
        for (int mt = 0; mt < 4; ++mt){
            int row = m_off + mt*16 + (lane & 15);
            ldsm_x4(a[mt], sA + (uint32_t)(row*40 + k16 + ((lane>>4)<<3))*2);
        }
        uint32_t bfr[4][4];
        #pragma unroll
        for (int np = 0; np < 4; ++np){
            int row = n_off + np*16 + (lane & 7) + ((lane>>4)&1)*8;
            ldsm_x4(bfr[np], sB + (uint32_t)(row*40 + k16 + (((lane>>3)&1)<<3))*2);
        }
        #pragma unroll
        for (int mt = 0; mt < 4; ++mt)
            #pragma unroll
            for (int nt = 0; nt < 8; ++nt)
                mma16816(c[mt][nt], a[mt], &bfr[nt>>1][(nt&1)*2]);
    }
}

// ---------------- preprocessing kernels ------------------------------------
__global__ void k_bits(const int* __restrict__ adj, const int* __restrict__ mask){
    int warp = threadIdx.x >> 5, lane = threadIdx.x & 31;
    int r = blockIdx.x * 8 + warp;
    int b = (r / N_) % B_;
    int i = r % N_;
    int mi = mask[b*N_ + i];
    const int* arow = adj + (size_t)r * N_;
    unsigned keep = 0;
    #pragma unroll
    for (int c = 0; c < 8; c++){
        int j = c*32 + lane;
        int bit = mi && mask[b*N_ + j] && arow[j] && (j != i);
        unsigned wrd = __ballot_sync(0xffffffffu, bit != 0);
        if (lane == c) keep = wrd;
    }
    if (lane < 8) g_bits[(size_t)r*8 + lane] = keep;
}
__global__ void k_neigh(){
    int t = blockIdx.x*blockDim.x + threadIdx.x;
    int b = t / N_;
    int s = 0;
    for (int e = 0; e < E_; e++){
        const unsigned* row = g_bits + (size_t)((e*B_+b)*N_ + (t % N_))*8;
        #pragma unroll
        for (int c = 0; c < 8; c++) s += __popc(row[c]);
    }
    float n = (float)s; if (n < 1.f) n = 1.f;
    g_invneigh[t] = 1.f / n;
}
__global__ void k_bstack(const float* __restrict__ We, const float* __restrict__ Ws){
    int idx = blockIdx.x*256 + threadIdx.x;
    if (idx >= D_*KB_) return;
    int d = idx / KB_, kk = idx % KB_;
    float w;
    if (kk < KX_){
        int e = kk / D_, k2 = kk % D_;
        w = We[((size_t)e*D_ + d)*D_ + k2];
    } else {
        w = Ws[(size_t)d*D_ + (kk - KX_)];
    }
    g_Bstack[(size_t)d*KB_ + kk] = __float2half(w);
}
// build global packed permutation: actives of all batches first
__global__ void k_perm(const int* __restrict__ mask){
    __shared__ int cnts[B_];
    int b = threadIdx.x;
    if (b < B_){
        int c = 0;
        for (int i = 0; i < N_; ++i) c += (mask[b*N_+i] != 0);
        cnts[b] = c;
    }
    __syncthreads();
    if (threadIdx.x == 0){
        int a = 0;
        for (int b2 = 0; b2 < B_; ++b2){ g_aoff[b2] = a; a += cnts[b2]; }
        g_aoff[B_] = a; g_acnt = a;
    }
    __syncthreads();
    if (b < B_){
        int apos = g_aoff[b];
        int mpos = g_aoff[B_] + (b*N_ - g_aoff[b]);
        for (int i = 0; i < N_; ++i){
            int orig = b*N_ + i;
            if (mask[orig]) g_gperm[apos++] = orig;
            else            g_gperm[mpos++] = orig;
        }
        g_cnt[b] = cnts[b];
    }
}
// zero Xhi padding rows [ACNT, ceil128(ACNT))
__global__ void k_zeroX(){
    int r = g_acnt + blockIdx.y;
    if (r >= M_ || r >= ((g_acnt + 127) & ~127)) return;
    int c = blockIdx.x*256 + threadIdx.x;      // 0..2559 u32 cols
    ((uint32_t*)(g_Xhi + (size_t)r*KX_))[c] = 0u;
}

// ---------------- per-iteration elementwise kernels -------------------------
__global__ void k_w(const float* __restrict__ node0, int useScratch,
                    const float* __restrict__ Wnw, const float* __restrict__ bnw,
                    float* __restrict__ woutBase, int it){
    int warp = threadIdx.x >> 5, lane = threadIdx.x & 31;
    int r = blockIdx.x*8 + warp;
    const float* node = useScratch ? g_nodeA : node0;
    const float4* nr = (const float4*)(node + (size_t)r*D_);
    const float4* wr = (const float4*)Wnw;
    float s = 0.f;
    #pragma unroll
    for (int c = 0; c < 4; c++){
        float4 a = nr[c*32 + lane], w = wr[c*32 + lane];
        s += a.x*w.x + a.y*w.y + a.z*w.z + a.w*w.w;
    }
    #pragma unroll
    for (int o = 16; o; o >>= 1) s += __shfl_down_sync(0xffffffffu, s, o);
    if (lane == 0){
        float z = s + bnw[0];
        float w = 1.f / (1.f + expf(-z));
        g_w[r] = w;
        int b = r / N_, n = r % N_;
        woutBase[(size_t)b*(2*N_) + it*N_ + n] = w;
    }
}
__global__ void k_zt(const float* __restrict__ node0, int useScratch){
    __shared__ float s[32][33];
    const float* node = useScratch ? g_nodeA : node0;
    int b = blockIdx.z, d0 = blockIdx.x*32, j0 = blockIdx.y*32;
    int tx = threadIdx.x, ty = threadIdx.y;
    int j = j0 + ty;
    size_t gidx = ((size_t)b*N_ + j)*D_ + d0 + tx;
    float raw = node[gidx];
    if (!useScratch) g_nhi[gidx] = __float2half(raw);
    s[ty][tx] = raw * g_w[b*N_ + j];
    __syncthreads();
    g_Zt[((size_t)b*D_ + d0 + ty)*N_ + j0 + tx] = __float2half(s[tx][ty]);
}

// ---------------- stage A GEMM: Xhi[rank] = fp16((G@Zt)*inv_neigh) ----------
// packed M: only active rows of each batch; tile-1 exits if cnt<=128.
__global__ void __launch_bounds__(256, 1) k_gemmA(){
    extern __shared__ char dsm[];
    uint32_t sbase = smem_u32(dsm);
    int tid = threadIdx.x, wid = tid >> 5, lane = tid & 31;
    int dBase = blockIdx.x * 256;           // 0 or 256
    int y = blockIdx.y;                     // be*2 + mhalf
    int mhalf = y & 1; int be = y >> 1;
    int e = be % E_, b = be / E_;
    int cnt = g_cnt[b];
    int mBase = mhalf * 128;
    if (mBase >= cnt) return;
    int aoff = g_aoff[b];
    int m_off = (wid >> 2) * 64;
    int n_off = (wid & 3) * 64;

    const fp16* Zbase = g_Zt + ((size_t)b*D_ + dBase) * (size_t)N_;
    const unsigned* bitbase = g_bits + (size_t)((size_t)e*B_ + b)*N_*8;

    int rA = tid >> 1, hsel = tid & 1;
    int rankA = mBase + rA;
    bool av = rankA < cnt;
    int iloc = av ? (g_gperm[aoff + rankA] - b*N_) : 0;

    auto loadB = [&](int itk, int s){
        uint32_t sB = sbase + s*STG_BYTES + OFF_B;
        const fp16* src = Zbase + (size_t)tid*N_ + itk*32;
        uint32_t d0 = sB + (uint32_t)(tid*40)*2;
        cpa16(d0,      src);
        cpa16(d0 + 16, src + 8);
        cpa16(d0 + 32, src + 16);
        cpa16(d0 + 48, src + 24);
        CP_COMMIT();
    };
    auto expandA = [&](int itk, int s){
        unsigned w32 = av ? bitbase[(size_t)iloc*8 + (itk & 7)] : 0u;
        unsigned bits = (w32 >> (hsel*16)) & 0xFFFFu;
        uint32_t u[8];
        #pragma unroll
        for (int q = 0; q < 8; ++q){
            u[q] = ((bits >> (2*q)) & 1u ? 0x3C00u : 0u)
                 | ((bits >> (2*q+1)) & 1u ? 0x3C000000u : 0u);
        }
        char* dst = dsm + s*STG_BYTES + (rA*40 + hsel*16)*2;
        *(uint4*)(dst)      = make_uint4(u[0],u[1],u[2],u[3]);
        *(uint4*)(dst + 16) = make_uint4(u[4],u[5],u[6],u[7]);
    };

    float c[4][8][4];
    #pragma unroll
    for (int i = 0; i < 4; ++i)
        #pragma unroll
        for (int j = 0; j < 8; ++j)
            #pragma unroll
            for (int q = 0; q < 4; ++q) c[i][j][q] = 0.f;

    expandA(0, 0);
    loadB(0, 0); loadB(1, 1); loadB(2, 2);
    for (int it = 0; it < KI_A; ++it){
        CP_WAIT2();
        __syncthreads();
        if (it + 1 < KI_A) expandA(it + 1, (it + 1) & 3);
        if (it + 3 < KI_A) loadB(it + 3, (it + 3) & 3); else CP_COMMIT();
        int s = it & 3;
        warp_compute(sbase + s*STG_BYTES, sbase + s*STG_BYTES + OFF_B,
                     m_off, n_off, c, lane);
    }

    // epilogue: * inv_neigh, fp16 store to packed rank rows (predicated)
    #pragma unroll
    for (int mt = 0; mt < 4; ++mt){
        int rk1 = mBase + m_off + mt*16 + (lane >> 2);
        int rk2 = rk1 + 8;
        bool v1 = rk1 < cnt, v2 = rk2 < cnt;
        float inv1 = 0.f, inv2 = 0.f;
        int gr1 = aoff + rk1, gr2 = aoff + rk2;
        if (v1) inv1 = g_invneigh[g_gperm[gr1]];
        if (v2) inv2 = g_invneigh[g_gperm[gr2]];
        #pragma unroll
        for (int nt = 0; nt < 8; ++nt){
            int col = e*D_ + dBase + n_off + nt*8 + (lane & 3)*2;
            if (v1){
                fp16 h0 = __float2half(c[mt][nt][0]*inv1);
                fp16 h1 = __float2half(c[mt][nt][1]*inv1);
                *(uint32_t*)(g_Xhi + (size_t)gr1*KX_ + col) =
                    (uint32_t)__half_as_ushort(h0) | ((uint32_t)__half_as_ushort(h1) << 16);
            }
            if (v2){
                fp16 h2 = __float2half(c[mt][nt][2]*inv2);
                fp16 h3 = __float2half(c[mt][nt][3]*inv2);
                *(uint32_t*)(g_Xhi + (size_t)gr2*KX_ + col) =
                    (uint32_t)__half_as_ushort(h2) | ((uint32_t)__half_as_ushort(h3) << 16);
            }
        }
    }
}

// ---------------- stage B GEMM (rank space): out = relu([X|n]@W + b) --------
// tiles with mBase >= ACNT run only the self K-segment (kStart=160).
__global__ void __launch_bounds__(256, 1) k_gemmB(const float* __restrict__ bself,
                                                  float* __restrict__ out0,
                                                  int srcSel, int outMode){
    extern __shared__ char dsm[];
    uint32_t sbase = smem_u32(dsm);
    int tid = threadIdx.x, wid = tid >> 5, lane = tid & 31;
    int dBase = blockIdx.x * 256;
    int mBase = blockIdx.y * 128;
    int m_off = (wid >> 2) * 64;
    int n_off = (wid & 3) * 64;
    int acnt = g_acnt;
    int kStart = (mBase >= acnt) ? KSLF : 0;

    const fp16* NHI = srcSel ? g_nhi2 : g_nhi;
    int rA = tid >> 1, cA = (tid & 1)*2;
    int morig = g_gperm[mBase + rA];         // orig row for self-segment gather

    auto load = [&](int itk, int s){
        uint32_t sA = sbase + s*STG_BYTES;
        uint32_t sB = sA + OFF_B;
        int rr = itk * 32;
        const fp16* Arow;
        if (rr < KX_) Arow = g_Xhi + (size_t)(mBase + rA)*KX_ + rr;
        else          Arow = NHI + (size_t)morig*D_ + (rr - KX_);
        uint32_t dA = sA + (uint32_t)(rA*40 + cA*8)*2;
        cpa16(dA,      Arow + cA*8);
        cpa16(dA + 16, Arow + cA*8 + 8);
        const fp16* Bb = g_Bstack + (size_t)(dBase + tid)*KB_ + rr;
        uint32_t dB = sB + (uint32_t)(tid*40)*2;
        cpa16(dB,      Bb);
        cpa16(dB + 16, Bb + 8);
        cpa16(dB + 32, Bb + 16);
        cpa16(dB + 48, Bb + 24);
        CP_COMMIT();
    };

    float c[4][8][4];
    #pragma unroll
    for (int i = 0; i < 4; ++i)
        #pragma unroll
        for (int j = 0; j < 8; ++j)
            #pragma unroll
            for (int q = 0; q < 4; ++q) c[i][j][q] = 0.f;

    load(kStart, 0); load(kStart+1, 1); load(kStart+2, 2);
    for (int it = kStart; it < KI_B; ++it){
        CP_WAIT2();
        __syncthreads();
        if (it + 3 < KI_B) load(it + 3, (it + 3 - kStart) & 3); else CP_COMMIT();
        int s = (it - kStart) & 3;
        warp_compute(sbase + s*STG_BYTES, sbase + s*STG_BYTES + OFF_B,
                     m_off, n_off, c, lane);
    }

    #pragma unroll
    for (int mt = 0; mt < 4; ++mt){
        int m1 = mBase + m_off + mt*16 + (lane >> 2);
        int o1 = g_gperm[m1], o2 = g_gperm[m1 + 8];
        #pragma unroll
        for (int nt = 0; nt < 8; ++nt){
            int n = dBase + n_off + nt*8 + (lane & 3)*2;
            float bi0 = __ldg(bself + n), bi1 = __ldg(bself + n + 1);
            float v0 = c[mt][nt][0] + bi0, v1 = c[mt][nt][1] + bi1;
            float v2 = c[mt][nt][2] + bi0, v3 = c[mt][nt][3] + bi1;
            v0 = v0 > 0.f ? v0 : 0.f; v1 = v1 > 0.f ? v1 : 0.f;
            v2 = v2 > 0.f ? v2 : 0.f; v3 = v3 > 0.f ? v3 : 0.f;
            if (outMode){
                *(float2*)(g_nodeA + (size_t)o1*D_ + n) = make_float2(v0, v1);
                *(float2*)(g_nodeA + (size_t)o2*D_ + n) = make_float2(v2, v3);
                fp16 h0=__float2half(v0), h1=__float2half(v1);
                fp16 h2=__float2half(v2), h3=__float2half(v3);
                *(uint32_t*)(g_nhi2 + (size_t)o1*D_ + n) = (uint32_t)__half_as_ushort(h0)|((uint32_t)__half_as_ushort(h1)<<16);
                *(uint32_t*)(g_nhi2 + (size_t)o2*D_ + n) = (uint32_t)__half_as_ushort(h2)|((uint32_t)__half_as_ushort(h3)<<16);
            } else {
                *(float2*)(out0 + (size_t)o1*D_ + n) = make_float2(v0, v1);
                *(float2*)(out0 + (size_t)o2*D_ + n) = make_float2(v2, v3);
            }
        }
    }
}

// ---------------- launch ----------------------------------------------------
extern "C" void kernel_launch(void* const* d_in, const int* in_sizes, int n_in,
                              void* d_out, int out_size){
    const float* node  = (const float*)d_in[0];
    const float* Wnw   = (const float*)d_in[1];
    const float* bnw   = (const float*)d_in[2];
    const float* Wself = (const float*)d_in[3];
    const float* bself = (const float*)d_in[4];
    const float* Wedge = (const float*)d_in[5];
    const int*   mask  = (const int*)d_in[6];
    const int*   adj   = (const int*)d_in[7];

    float* out  = (float*)d_out;
    float* outW = out + (size_t)M_*D_;

    cudaFuncSetAttribute(k_gemmA, cudaFuncAttributeMaxDynamicSharedMemorySize, SMEM_DYN);
    cudaFuncSetAttribute(k_gemmB, cudaFuncAttributeMaxDynamicSharedMemorySize, SMEM_DYN);

    // iteration-invariant preprocessing
    k_bstack<<<(D_*KB_ + 255)/256, 256>>>(Wedge, Wself);
    k_bits  <<<(E_*B_*N_)/8, 256>>>(adj, mask);
    k_neigh <<<M_/256, 256>>>();
    k_perm  <<<1, 64>>>(mask);
    k_zeroX <<<dim3(10, 128), 256>>>();

    // ---- iteration 0: node -> g_nodeA (+ nhi2) ----
    k_w    <<<M_/8, 256>>>(node, 0, Wnw, bnw, outW, 0);
    k_zt   <<<dim3(16, 8, B_), dim3(32, 32)>>>(node, 0);
    k_gemmA<<<dim3(2, B_*E_*2), 256, SMEM_DYN>>>();
    k_gemmB<<<dim3(2, M_/128), 256, SMEM_DYN>>>(bself, out, 0, 1);

    // ---- iteration 1: g_nodeA -> d_out ----
    k_w    <<<M_/8, 256>>>(node, 1, Wnw, bnw, outW, 1);
    k_zt   <<<dim3(16, 8, B_), dim3(32, 32)>>>(node, 1);
    k_gemmA<<<dim3(2, B_*E_*2), 256, SMEM_DYN>>>();
    k_gemmB<<<dim3(2, M_/128), 256, SMEM_DYN>>>(bself, out, 1, 0);
}

// round 9
// speedup vs baseline: 6.7070x; 1.1181x over previous
#include <cuda_runtime.h>
#include <cuda_fp16.h>
#include <math.h>
#include <stdint.h>

// ---------------- problem constants ----------------
#define B_  64
#define N_  256
#define D_  512
#define E_  10
#define M_  (B_*N_)        // 16384
#define KX_ (E_*D_)        // 5120  (edge part of stage-B K)
#define KB_ (KX_+D_)       // 5632  (edge-hi + self-hi)
#define KI_B (KB_/32)      // 176 k-iters (stage B)
#define KSLF (KX_/32)      // 160 = k-iter where self segment starts

typedef __half fp16;

// ---------------- device scratch (static; no runtime allocation) ----------
__device__ unsigned g_bits[(size_t)E_*B_*N_*8];      // graphs bitmask, packed-j rank space
__device__ float    g_invneigh[M_];
__device__ float    g_w[M_];
__device__ float    g_nodeA[(size_t)M_*D_];          // fp32 node ping buffer
__device__ fp16     g_Bstack[(size_t)D_*KB_];        // [d][kk]: Wedge_hi | Wself_hi
__device__ fp16     g_Zt[(size_t)B_*D_*N_];          // [b][d][jr] packed ranks, zero-pad
__device__ fp16     g_Xhi[(size_t)M_*KX_];           // packed-rank rows
__device__ fp16     g_nhi[(size_t)M_*D_], g_nhi2[(size_t)M_*D_];
// mask packing
__device__ int      g_gperm[M_];     // rank -> orig row (actives first, global)
__device__ int      g_cnt[B_];       // active count per batch
__device__ int      g_aoff[B_+1];    // prefix of g_cnt
__device__ int      g_acnt;          // total active rows

// ---------------- PTX helpers ----------------------------------------------
__device__ __forceinline__ uint32_t smem_u32(const void* p){
    uint32_t a; asm("{ .reg .u64 t; cvta.to.shared.u64 t, %1; cvt.u32.u64 %0, t; }"
                    : "=r"(a) : "l"(p)); return a;
}
__device__ __forceinline__ void cpa16(uint32_t dst, const void* src){
    asm volatile("cp.async.cg.shared.global [%0], [%1], 16;" :: "r"(dst), "l"(src));
}
#define CP_COMMIT() asm volatile("cp.async.commit_group;" ::: "memory")
#define CP_WAIT2()  asm volatile("cp.async.wait_group 2;" ::: "memory")

__device__ __forceinline__ void ldsm_x4(uint32_t* r, uint32_t addr){
    asm volatile("ldmatrix.sync.aligned.m8n8.x4.shared.b16 {%0,%1,%2,%3}, [%4];"
        : "=r"(r[0]),"=r"(r[1]),"=r"(r[2]),"=r"(r[3]) : "r"(addr));
}
__device__ __forceinline__ void mma16816(float* c, const uint32_t* a, const uint32_t* b){
    asm volatile("mma.sync.aligned.m16n8k16.row.col.f32.f16.f16.f32 "
        "{%0,%1,%2,%3},{%4,%5,%6,%7},{%8,%9},{%0,%1,%2,%3};"
        : "+f"(c[0]),"+f"(c[1]),"+f"(c[2]),"+f"(c[3])
        : "r"(a[0]),"r"(a[1]),"r"(a[2]),"r"(a[3]), "r"(b[0]),"r"(b[1]));
}

// gemmB smem: 4 stages, As[128][40]+Bs[256][40]
#define STG_B  30720
#define OFFB_B 10240
#define SMEM_B_DYN (4*STG_B)
// gemmA smem: 4 stages, As[64][40]+Bs[256][40]
#define STG_A  25600
#define OFFB_A 5120
#define SMEM_A_DYN (4*STG_A)

// warp tile MTx16 x 64 (MT m-fragments, 8 n-fragments)
template<int MT>
__device__ __forceinline__ void warp_compute_t(uint32_t sA, uint32_t sB,
                                               int m_off, int n_off,
                                               float c[][8][4], int lane){
    #pragma unroll
    for (int kh = 0; kh < 2; ++kh){
        int k16 = kh*16;
        uint32_t a[MT][4];
        #pragma unroll
        for (int mt = 0; mt < MT; ++mt){
            int row = m_off + mt*16 + (lane & 15);
            ldsm_x4(a[mt], sA + (uint32_t)(row*40 + k16 + ((lane>>4)<<3))*2);
        }
        uint32_t bfr[4][4];
        #pragma unroll
        for (int np = 0; np < 4; ++np){
            int row = n_off + np*16 + (lane & 7) + ((lane>>4)&1)*8;
            ldsm_x4(bfr[np], sB + (uint32_t)(row*40 + k16 + (((lane>>3)&1)<<3))*2);
        }
        #pragma unroll
        for (int mt = 0; mt < MT; ++mt)
            #pragma unroll
            for (int nt = 0; nt < 8; ++nt)
                mma16816(c[mt][nt], a[mt], &bfr[nt>>1][(nt&1)*2]);
    }
}

// ---------------- preprocessing kernels ------------------------------------
// parallel permutation build: warp per batch, ballot prefix
__global__ void k_perm(const int* __restrict__ mask){
    __shared__ int sc[B_+1];
    int wid = threadIdx.x >> 5, lane = threadIdx.x & 31;
    for (int b = wid; b < B_; b += 32){
        int cnt = 0;
        #pragma unroll
        for (int c = 0; c < 8; ++c){
            unsigned bal = __ballot_sync(0xffffffffu, mask[b*N_ + c*32 + lane] != 0);
            cnt += __popc(bal);
        }
        if (lane == 0){ sc[b] = cnt; g_cnt[b] = cnt; }
    }
    __syncthreads();
    if (threadIdx.x == 0){
        int a = 0;
        for (int b = 0; b < B_; ++b){ g_aoff[b] = a; int t = sc[b]; sc[b] = a; a += t; }
        g_aoff[B_] = a; g_acnt = a; sc[B_] = a;
    }
    __syncthreads();
    for (int b = wid; b < B_; b += 32){
        int apos = sc[b];
        int mpos = sc[B_] + (b*N_ - sc[b]);
        #pragma unroll
        for (int c = 0; c < 8; ++c){
            int orig = b*N_ + c*32 + lane;
            int bit = mask[orig] != 0;
            unsigned bal = __ballot_sync(0xffffffffu, bit);
            unsigned ltm = (1u << lane) - 1u;
            if (bit) g_gperm[apos + __popc(bal & ltm)] = orig;
            else     g_gperm[mpos + __popc(~bal & ltm)] = orig;
            apos += __popc(bal);
            mpos += 32 - __popc(bal);
        }
    }
}
// bitmask in packed-j rank space: bit jr set iff edge (i, perm[jr]) survives
__global__ void k_bits(const int* __restrict__ adj, const int* __restrict__ mask){
    int warp = threadIdx.x >> 5, lane = threadIdx.x & 31;
    int r = blockIdx.x * 8 + warp;          // (e*B+b)*N + i
    int b = (r / N_) % B_;
    int i = r % N_;
    int mi = mask[b*N_ + i];
    int cnt = g_cnt[b], aoff = g_aoff[b];
    const int* arow = adj + (size_t)r * N_;
    unsigned keep = 0;
    #pragma unroll
    for (int c = 0; c < 8; c++){
        int jr = c*32 + lane;
        int jv = jr < cnt;
        int jloc = jv ? (g_gperm[aoff + jr] - b*N_) : 0;
        int bit = jv && mi && arow[jloc] && (jloc != i);
        unsigned wrd = __ballot_sync(0xffffffffu, bit != 0);
        if (lane == c) keep = wrd;
    }
    if (lane < 8) g_bits[(size_t)r*8 + lane] = keep;
}
__global__ void k_neigh(){
    int t = blockIdx.x*blockDim.x + threadIdx.x;
    int b = t / N_;
    int s = 0;
    for (int e = 0; e < E_; e++){
        const unsigned* row = g_bits + (size_t)((e*B_+b)*N_ + (t % N_))*8;
        #pragma unroll
        for (int c = 0; c < 8; c++) s += __popc(row[c]);
    }
    float n = (float)s; if (n < 1.f) n = 1.f;
    g_invneigh[t] = 1.f / n;
}
__global__ void k_bstack(const float* __restrict__ We, const float* __restrict__ Ws){
    int idx = blockIdx.x*256 + threadIdx.x;
    if (idx >= D_*KB_) return;
    int d = idx / KB_, kk = idx % KB_;
    float w;
    if (kk < KX_){
        int e = kk / D_, k2 = kk % D_;
        w = We[((size_t)e*D_ + d)*D_ + k2];
    } else {
        w = Ws[(size_t)d*D_ + (kk - KX_)];
    }
    g_Bstack[(size_t)d*KB_ + kk] = __float2half(w);
}
// zero Xhi padding rows [ACNT, ceil128(ACNT))
__global__ void k_zeroX(){
    int r = g_acnt + blockIdx.y;
    if (r >= M_ || r >= ((g_acnt + 127) & ~127)) return;
    int c = blockIdx.x*256 + threadIdx.x;
    ((uint32_t*)(g_Xhi + (size_t)r*KX_))[c] = 0u;
}

// ---------------- per-iteration elementwise kernels -------------------------
// gate w; on iter 0 also writes g_nhi (fp16 of node) for ALL rows
__global__ void k_w(const float* __restrict__ node0, int useScratch,
                    const float* __restrict__ Wnw, const float* __restrict__ bnw,
                    float* __restrict__ woutBase, int it){
    int warp = threadIdx.x >> 5, lane = threadIdx.x & 31;
    int r = blockIdx.x*8 + warp;
    const float* node = useScratch ? g_nodeA : node0;
    const float4* nr = (const float4*)(node + (size_t)r*D_);
    const float4* wr = (const float4*)Wnw;
    float s = 0.f;
    #pragma unroll
    for (int c = 0; c < 4; c++){
        float4 a = nr[c*32 + lane], w = wr[c*32 + lane];
        s += a.x*w.x + a.y*w.y + a.z*w.z + a.w*w.w;
        if (!useScratch){
            fp16 h0=__float2half(a.x), h1=__float2half(a.y);
            fp16 h2=__float2half(a.z), h3=__float2half(a.w);
            uint2 pk;
            pk.x = (uint32_t)__half_as_ushort(h0) | ((uint32_t)__half_as_ushort(h1) << 16);
            pk.y = (uint32_t)__half_as_ushort(h2) | ((uint32_t)__half_as_ushort(h3) << 16);
            *(uint2*)(g_nhi + (size_t)r*D_ + (c*32 + lane)*4) = pk;
        }
    }
    #pragma unroll
    for (int o = 16; o; o >>= 1) s += __shfl_down_sync(0xffffffffu, s, o);
    if (lane == 0){
        float z = s + bnw[0];
        float w = 1.f / (1.f + expf(-z));
        g_w[r] = w;
        int b = r / N_, n = r % N_;
        woutBase[(size_t)b*(2*N_) + it*N_ + n] = w;
    }
}
// transpose w*node into packed-j rank space; zero-pad jr >= cnt
__global__ void k_zt(const float* __restrict__ node0, int useScratch){
    __shared__ float s[32][33];
    const float* node = useScratch ? g_nodeA : node0;
    int b = blockIdx.z, d0 = blockIdx.x*32, j0 = blockIdx.y*32;
    int tx = threadIdx.x, ty = threadIdx.y;
    int jr = j0 + ty;
    int cnt = g_cnt[b], aoff = g_aoff[b];
    float v = 0.f;
    if (jr < cnt){
        int orig = g_gperm[aoff + jr];
        v = node[(size_t)orig*D_ + d0 + tx] * g_w[orig];
    }
    s[ty][tx] = v;
    __syncthreads();
    g_Zt[((size_t)b*D_ + d0 + ty)*N_ + j0 + tx] = __float2half(s[tx][ty]);
}

// ---------------- stage A GEMM: Xhi[rank] = fp16((G@Zt)*inv_neigh) ----------
// CTA tile 64x256 (m-tile 64), K packed to ceil(cnt/32)*32
__global__ void __launch_bounds__(256, 1) k_gemmA(){
    extern __shared__ char dsm[];
    uint32_t sbase = smem_u32(dsm);
    int tid = threadIdx.x, wid = tid >> 5, lane = tid & 31;
    int dBase = blockIdx.x * 256;           // 0 or 256
    int y = blockIdx.y;                     // be*4 + mq
    int mq = y & 3; int be = y >> 2;
    int e = be % E_, b = be / E_;
    int cnt = g_cnt[b];
    int mBase = mq * 64;
    if (mBase >= cnt) return;
    int aoff = g_aoff[b];
    int m_off = (wid >> 2) * 32;
    int n_off = (wid & 3) * 64;
    int KI = (cnt + 31) >> 5;

    const fp16* Zbase = g_Zt + ((size_t)b*D_ + dBase) * (size_t)N_;
    const unsigned* bitbase = g_bits + (size_t)((size_t)e*B_ + b)*N_*8;

    int rA = tid >> 2, qsel = tid & 3;      // A expand: row 0..63, 8-bit quarter
    int rankA = mBase + rA;
    bool av = rankA < cnt;
    int iloc = av ? (g_gperm[aoff + rankA] - b*N_) : 0;

    auto loadB = [&](int itk, int s){
        uint32_t sB = sbase + s*STG_A + OFFB_A;
        const fp16* src = Zbase + (size_t)tid*N_ + itk*32;
        uint32_t d0 = sB + (uint32_t)(tid*40)*2;
        cpa16(d0,      src);
        cpa16(d0 + 16, src + 8);
        cpa16(d0 + 32, src + 16);
        cpa16(d0 + 48, src + 24);
        CP_COMMIT();
    };
    auto expandA = [&](int itk, int s){
        unsigned w32 = av ? bitbase[(size_t)iloc*8 + itk] : 0u;
        unsigned bits8 = (w32 >> (qsel*8)) & 0xFFu;
        uint32_t u[4];
        #pragma unroll
        for (int q = 0; q < 4; ++q){
            u[q] = ((bits8 >> (2*q)) & 1u ? 0x3C00u : 0u)
                 | ((bits8 >> (2*q+1)) & 1u ? 0x3C000000u : 0u);
        }
        *(uint4*)(dsm + s*STG_A + (rA*40 + qsel*8)*2) = make_uint4(u[0],u[1],u[2],u[3]);
    };

    float c[2][8][4];
    #pragma unroll
    for (int i = 0; i < 2; ++i)
        #pragma unroll
        for (int j = 0; j < 8; ++j)
            #pragma unroll
            for (int q = 0; q < 4; ++q) c[i][j][q] = 0.f;

    expandA(0, 0);
    loadB(0, 0); loadB(1, 1); loadB(2, 2);   // beyond-KI loads hit zero-padded Zt
    for (int it = 0; it < KI; ++it){
        CP_WAIT2();
        __syncthreads();
        if (it + 1 < KI) expandA(it + 1, (it + 1) & 3);
        if (it + 3 < KI) loadB(it + 3, (it + 3) & 3); else CP_COMMIT();
        int s = it & 3;
        warp_compute_t<2>(sbase + s*STG_A, sbase + s*STG_A + OFFB_A,
                          m_off, n_off, c, lane);
    }

    // epilogue: * inv_neigh, fp16 store to packed rank rows
    #pragma unroll
    for (int mt = 0; mt < 2; ++mt){
        int rk1 = mBase + m_off + mt*16 + (lane >> 2);
        int rk2 = rk1 + 8;
        bool v1 = rk1 < cnt, v2 = rk2 < cnt;
        float inv1 = 0.f, inv2 = 0.f;
        int gr1 = aoff + rk1, gr2 = aoff + rk2;
        if (v1) inv1 = g_invneigh[g_gperm[gr1]];
        if (v2) inv2 = g_invneigh[g_gperm[gr2]];
        #pragma unroll
        for (int nt = 0; nt < 8; ++nt){
            int col = e*D_ + dBase + n_off + nt*8 + (lane & 3)*2;
            if (v1){
                fp16 h0 = __float2half(c[mt][nt][0]*inv1);
                fp16 h1 = __float2half(c[mt][nt][1]*inv1);
                *(uint32_t*)(g_Xhi + (size_t)gr1*KX_ + col) =
                    (uint32_t)__half_as_ushort(h0) | ((uint32_t)__half_as_ushort(h1) << 16);
            }
            if (v2){
                fp16 h2 = __float2half(c[mt][nt][2]*inv2);
                fp16 h3 = __float2half(c[mt][nt][3]*inv2);
                *(uint32_t*)(g_Xhi + (size_t)gr2*KX_ + col) =
                    (uint32_t)__half_as_ushort(h2) | ((uint32_t)__half_as_ushort(h3) << 16);
            }
        }
    }
}

// ---------------- stage B GEMM (rank space): out = relu([X|n]@W + b) --------
__global__ void __launch_bounds__(256, 1) k_gemmB(const float* __restrict__ bself,
                                                  float* __restrict__ out0,
                                                  int srcSel, int outMode){
    extern __shared__ char dsm[];
    uint32_t sbase = smem_u32(dsm);
    int tid = threadIdx.x, wid = tid >> 5, lane = tid & 31;
    int dBase = blockIdx.x * 256;
    int mBase = blockIdx.y * 128;
    int m_off = (wid >> 2) * 64;
    int n_off = (wid & 3) * 64;
    int acnt = g_acnt;
    int kStart = (mBase >= acnt) ? KSLF : 0;

    const fp16* NHI = srcSel ? g_nhi2 : g_nhi;
    int rA = tid >> 1, cA = (tid & 1)*2;
    int morig = g_gperm[mBase + rA];

    auto load = [&](int itk, int s){
        uint32_t sA = sbase + s*STG_B;
        uint32_t sB = sA + OFFB_B;
        int rr = itk * 32;
        const fp16* Arow;
        if (rr < KX_) Arow = g_Xhi + (size_t)(mBase + rA)*KX_ + rr;
        else          Arow = NHI + (size_t)morig*D_ + (rr - KX_);
        uint32_t dA = sA + (uint32_t)(rA*40 + cA*8)*2;
        cpa16(dA,      Arow + cA*8);
        cpa16(dA + 16, Arow + cA*8 + 8);
        const fp16* Bb = g_Bstack + (size_t)(dBase + tid)*KB_ + rr;
        uint32_t dB = sB + (uint32_t)(tid*40)*2;
        cpa16(dB,      Bb);
        cpa16(dB + 16, Bb + 8);
        cpa16(dB + 32, Bb + 16);
        cpa16(dB + 48, Bb + 24);
        CP_COMMIT();
    };

    float c[4][8][4];
    #pragma unroll
    for (int i = 0; i < 4; ++i)
        #pragma unroll
        for (int j = 0; j < 8; ++j)
            #pragma unroll
            for (int q = 0; q < 4; ++q) c[i][j][q] = 0.f;

    load(kStart, 0); load(kStart+1, 1); load(kStart+2, 2);
    for (int it = kStart; it < KI_B; ++it){
        CP_WAIT2();
        __syncthreads();
        if (it + 3 < KI_B) load(it + 3, (it + 3 - kStart) & 3); else CP_COMMIT();
        int s = (it - kStart) & 3;
        warp_compute_t<4>(sbase + s*STG_B, sbase + s*STG_B + OFFB_B,
                          m_off, n_off, c, lane);
    }

    #pragma unroll
    for (int mt = 0; mt < 4; ++mt){
        int m1 = mBase + m_off + mt*16 + (lane >> 2);
        int o1 = g_gperm[m1], o2 = g_gperm[m1 + 8];
        #pragma unroll
        for (int nt = 0; nt < 8; ++nt){
            int n = dBase + n_off + nt*8 + (lane & 3)*2;
            float bi0 = __ldg(bself + n), bi1 = __ldg(bself + n + 1);
            float v0 = c[mt][nt][0] + bi0, v1 = c[mt][nt][1] + bi1;
            float v2 = c[mt][nt][2] + bi0, v3 = c[mt][nt][3] + bi1;
            v0 = v0 > 0.f ? v0 : 0.f; v1 = v1 > 0.f ? v1 : 0.f;
            v2 = v2 > 0.f ? v2 : 0.f; v3 = v3 > 0.f ? v3 : 0.f;
            if (outMode){
                *(float2*)(g_nodeA + (size_t)o1*D_ + n) = make_float2(v0, v1);
                *(float2*)(g_nodeA + (size_t)o2*D_ + n) = make_float2(v2, v3);
                fp16 h0=__float2half(v0), h1=__float2half(v1);
                fp16 h2=__float2half(v2), h3=__float2half(v3);
                *(uint32_t*)(g_nhi2 + (size_t)o1*D_ + n) = (uint32_t)__half_as_ushort(h0)|((uint32_t)__half_as_ushort(h1)<<16);
                *(uint32_t*)(g_nhi2 + (size_t)o2*D_ + n) = (uint32_t)__half_as_ushort(h2)|((uint32_t)__half_as_ushort(h3)<<16);
            } else {
                *(float2*)(out0 + (size_t)o1*D_ + n) = make_float2(v0, v1);
                *(float2*)(out0 + (size_t)o2*D_ + n) = make_float2(v2, v3);
            }
        }
    }
}

// ---------------- launch ----------------------------------------------------
extern "C" void kernel_launch(void* const* d_in, const int* in_sizes, int n_in,
                              void* d_out, int out_size){
    const float* node  = (const float*)d_in[0];
    const float* Wnw   = (const float*)d_in[1];
    const float* bnw   = (const float*)d_in[2];
    const float* Wself = (const float*)d_in[3];
    const float* bself = (const float*)d_in[4];
    const float* Wedge = (const float*)d_in[5];
    const int*   mask  = (const int*)d_in[6];
    const int*   adj   = (const int*)d_in[7];

    float* out  = (float*)d_out;
    float* outW = out + (size_t)M_*D_;

    cudaFuncSetAttribute(k_gemmA, cudaFuncAttributeMaxDynamicSharedMemorySize, SMEM_A_DYN);
    cudaFuncSetAttribute(k_gemmB, cudaFuncAttributeMaxDynamicSharedMemorySize, SMEM_B_DYN);

    // iteration-invariant preprocessing
    k_bstack<<<(D_*KB_ + 255)/256, 256>>>(Wedge, Wself);
    k_perm  <<<1, 1024>>>(mask);
    k_bits  <<<(E_*B_*N_)/8, 256>>>(adj, mask);
    k_neigh <<<M_/256, 256>>>();
    k_zeroX <<<dim3(10, 128), 256>>>();

    // ---- iteration 0: node -> g_nodeA (+ nhi2) ----
    k_w    <<<M_/8, 256>>>(node, 0, Wnw, bnw, outW, 0);
    k_zt   <<<dim3(16, 8, B_), dim3(32, 32)>>>(node, 0);
    k_gemmA<<<dim3(2, B_*E_*4), 256, SMEM_A_DYN>>>();
    k_gemmB<<<dim3(2, M_/128), 256, SMEM_B_DYN>>>(bself, out, 0, 1);

    // ---- iteration 1: g_nodeA -> d_out ----
    k_w    <<<M_/8, 256>>>(node, 1, Wnw, bnw, outW, 1);
    k_zt   <<<dim3(16, 8, B_), dim3(32, 32)>>>(node, 1);
    k_gemmA<<<dim3(2, B_*E_*4), 256, SMEM_A_DYN>>>();
    k_gemmB<<<dim3(2, M_/128), 256, SMEM_B_DYN>>>(bself, out, 1, 0);
}